// round 7
// baseline (speedup 1.0000x reference)
#include <cuda_runtime.h>
#include <cstdint>

// ---------------- constants ----------------
#define NBLK   148
#define NTHR   256
#define KPH    3
#define MAXPER 48
#define MAXTOK 144
#define CTOK   145
#define HD     512
#define VOC    8000
#define BOSTOK 1
#define EOSTOK 2

// ---------------- scratch offsets (floats) ----------------
#define O_WZ    0u
#define O_MEM   49152u
#define O_CK    1622016u
#define O_CV    3194880u
#define O_QP    4767744u
#define O_KP    5029888u
#define O_VP    5292032u
#define O_SAB   5554176u
#define O_P1    5619712u
#define O_X1    6668288u
#define O_CQP   6733824u
#define O_CAB   7782400u
#define O_P2    7847936u
#define O_X2    8896512u
#define O_W1P   8962048u
#define O_ACT   10010624u
#define O_W2P   10272768u
#define O_KC    11321344u
#define O_VC    20824064u
#define F_TOTAL 30326784u

// d_out: tokens[128*144] | genm[128*144] | bounds[128*3] | hiddens[144*128*512]
#define OUT_GENM   18432
#define OUT_BOUNDS 36864
#define OUT_HID    37248

__device__ static __align__(128) float g_f[F_TOTAL];
__device__ static unsigned long long g_amax[MAXTOK * 128];
__device__ static unsigned g_count;
__device__ static volatile unsigned g_gen;

// ---------------- helpers ----------------
__device__ __forceinline__ float gelu_tanh(float x) {
    float x3 = x * x * x;
    return 0.5f * x * (1.0f + tanhf(0.7978845608028654f * (x + 0.044715f * x3)));
}
__device__ __forceinline__ float wred(float p) {
    p += __shfl_xor_sync(0xffffffffu, p, 16);
    p += __shfl_xor_sync(0xffffffffu, p, 8);
    p += __shfl_xor_sync(0xffffffffu, p, 4);
    p += __shfl_xor_sync(0xffffffffu, p, 2);
    p += __shfl_xor_sync(0xffffffffu, p, 1);
    return p;
}
__device__ __forceinline__ unsigned long long umax64(unsigned long long a, unsigned long long b) {
    return a > b ? a : b;
}

__device__ __forceinline__ void gsync() {
    __syncthreads();
    if (threadIdx.x == 0) {
        unsigned gen = g_gen;
        __threadfence();
        if (atomicAdd(&g_count, 1u) == (unsigned)(NBLK - 1)) {
            g_count = 0u;
            __threadfence();
            g_gen = gen + 1u;
        } else {
            while (g_gen == gen) __nanosleep(64);
        }
        __threadfence();
    }
    __syncthreads();
}

// ---------------- 128x64 tile core, BK=32, 4x8 microtile, prefetch pipelined ----------------
__device__ __forceinline__ void run_tile64(
    const float* __restrict__ A, const int* gidx, int lda,
    const float* __restrict__ W, int ldw, int wcol,
    int kOff, int kChunk, float* sA, float* sW, float acc[4][8])
{
    const int tid  = threadIdx.x;
    const int arow = tid >> 3, ak4 = (tid & 7) << 2;
    const int wn8  = (tid & 7) << 3;
    const int rg4  = (tid >> 3) << 2, cg8 = (tid & 7) << 3;

    const float* Arow[4];
#pragma unroll
    for (int i = 0; i < 4; i++) {
        int r = arow + (i << 5);
        int rr = gidx ? gidx[r] : r;
        Arow[i] = A + (size_t)rr * lda + kOff + ak4;
    }
    const float* Wp = W + (size_t)(kOff + arow) * ldw + wcol + wn8;

#pragma unroll
    for (int i = 0; i < 4; i++)
#pragma unroll
        for (int j = 0; j < 8; j++) acc[i][j] = 0.f;

    float4 pa0 = *(const float4*)(Arow[0]);
    float4 pa1 = *(const float4*)(Arow[1]);
    float4 pa2 = *(const float4*)(Arow[2]);
    float4 pa3 = *(const float4*)(Arow[3]);
    float4 pw0 = *(const float4*)(Wp);
    float4 pw1 = *(const float4*)(Wp + 4);

    for (int kt = 0; kt < kChunk; kt += 32) {
        sA[(ak4 + 0) * 132 + arow      ] = pa0.x;
        sA[(ak4 + 1) * 132 + arow      ] = pa0.y;
        sA[(ak4 + 2) * 132 + arow      ] = pa0.z;
        sA[(ak4 + 3) * 132 + arow      ] = pa0.w;
        sA[(ak4 + 0) * 132 + arow + 32 ] = pa1.x;
        sA[(ak4 + 1) * 132 + arow + 32 ] = pa1.y;
        sA[(ak4 + 2) * 132 + arow + 32 ] = pa1.z;
        sA[(ak4 + 3) * 132 + arow + 32 ] = pa1.w;
        sA[(ak4 + 0) * 132 + arow + 64 ] = pa2.x;
        sA[(ak4 + 1) * 132 + arow + 64 ] = pa2.y;
        sA[(ak4 + 2) * 132 + arow + 64 ] = pa2.z;
        sA[(ak4 + 3) * 132 + arow + 64 ] = pa2.w;
        sA[(ak4 + 0) * 132 + arow + 96 ] = pa3.x;
        sA[(ak4 + 1) * 132 + arow + 96 ] = pa3.y;
        sA[(ak4 + 2) * 132 + arow + 96 ] = pa3.z;
        sA[(ak4 + 3) * 132 + arow + 96 ] = pa3.w;
        *(float4*)&sW[arow * 64 + wn8    ] = pw0;
        *(float4*)&sW[arow * 64 + wn8 + 4] = pw1;
        __syncthreads();

        if (kt + 32 < kChunk) {
            pa0 = *(const float4*)(Arow[0] + kt + 32);
            pa1 = *(const float4*)(Arow[1] + kt + 32);
            pa2 = *(const float4*)(Arow[2] + kt + 32);
            pa3 = *(const float4*)(Arow[3] + kt + 32);
            pw0 = *(const float4*)(Wp + (size_t)(kt + 32) * ldw);
            pw1 = *(const float4*)(Wp + (size_t)(kt + 32) * ldw + 4);
        }

#pragma unroll
        for (int kk = 0; kk < 32; kk++) {
            float4 av  = *(const float4*)&sA[kk * 132 + rg4];
            float4 w0v = *(const float4*)&sW[kk * 64 + cg8];
            float4 w1v = *(const float4*)&sW[kk * 64 + cg8 + 4];
            acc[0][0] += av.x * w0v.x; acc[0][1] += av.x * w0v.y; acc[0][2] += av.x * w0v.z; acc[0][3] += av.x * w0v.w;
            acc[0][4] += av.x * w1v.x; acc[0][5] += av.x * w1v.y; acc[0][6] += av.x * w1v.z; acc[0][7] += av.x * w1v.w;
            acc[1][0] += av.y * w0v.x; acc[1][1] += av.y * w0v.y; acc[1][2] += av.y * w0v.z; acc[1][3] += av.y * w0v.w;
            acc[1][4] += av.y * w1v.x; acc[1][5] += av.y * w1v.y; acc[1][6] += av.y * w1v.z; acc[1][7] += av.y * w1v.w;
            acc[2][0] += av.z * w0v.x; acc[2][1] += av.z * w0v.y; acc[2][2] += av.z * w0v.z; acc[2][3] += av.z * w0v.w;
            acc[2][4] += av.z * w1v.x; acc[2][5] += av.z * w1v.y; acc[2][6] += av.z * w1v.z; acc[2][7] += av.z * w1v.w;
            acc[3][0] += av.w * w0v.x; acc[3][1] += av.w * w0v.y; acc[3][2] += av.w * w0v.z; acc[3][3] += av.w * w0v.w;
            acc[3][4] += av.w * w1v.x; acc[3][5] += av.w * w1v.y; acc[3][6] += av.w * w1v.z; acc[3][7] += av.w * w1v.w;
        }
        __syncthreads();
    }
}

__device__ __forceinline__ void store_tile64(float* __restrict__ C, int ldc, int colBase,
                                             const float acc[4][8])
{
    const int rg4 = (threadIdx.x >> 3) << 2, cg8 = (threadIdx.x & 7) << 3;
#pragma unroll
    for (int i = 0; i < 4; i++) {
        float* p = C + (size_t)(rg4 + i) * ldc + colBase + cg8;
        *(float4*)p       = make_float4(acc[i][0], acc[i][1], acc[i][2], acc[i][3]);
        *(float4*)(p + 4) = make_float4(acc[i][4], acc[i][5], acc[i][6], acc[i][7]);
    }
}

__device__ __forceinline__ float sum16(const float* p, int i) {
    float a = (p[i] + p[65536 + i]) + (p[131072 + i] + p[196608 + i]);
    float b = (p[262144 + i] + p[327680 + i]) + (p[393216 + i] + p[458752 + i]);
    float c = (p[524288 + i] + p[589824 + i]) + (p[655360 + i] + p[720896 + i]);
    float d = (p[786432 + i] + p[851968 + i]) + (p[917504 + i] + p[983040 + i]);
    return (a + b) + (c + d);
}

// ---------------- persistent mega-kernel ----------------
__global__ void __launch_bounds__(NTHR, 1) mega_kernel(
    const float* __restrict__ z_seq, const float* __restrict__ z_w,
    const float* __restrict__ Wl2d, const float* __restrict__ temb,
    const float* __restrict__ Wq,  const float* __restrict__ Wk,
    const float* __restrict__ Wv,  const float* __restrict__ Wo,
    const float* __restrict__ Wcq, const float* __restrict__ Wck,
    const float* __restrict__ Wcv, const float* __restrict__ Wco,
    const float* __restrict__ W1,  const float* __restrict__ W2,
    const float* __restrict__ Wout, float* __restrict__ out)
{
    __shared__ float sA[32 * 132];
    __shared__ float sW[32 * 64];
    __shared__ float s_q[8 * 64];
    __shared__ float s_sc[8 * 152];
    __shared__ int   s_act[384];
    __shared__ int   s_pos[128], s_tip[128], s_phr[128], s_done[128], s_nxt[128];
    __shared__ float s_gate[128];

    const int tid = threadIdx.x;
    const int bx  = blockIdx.x;
    const int gid = bx * NTHR + tid;
    const int gsz = NBLK * NTHR;
    float acc[4][8];

    float* wz  = g_f + O_WZ;
    float* mem = g_f + O_MEM;
    float* ckb = g_f + O_CK;
    float* cvb = g_f + O_CV;
    float* qp  = g_f + O_QP;
    float* kp  = g_f + O_KP;
    float* vp  = g_f + O_VP;
    float* sab = g_f + O_SAB;
    float* p1  = g_f + O_P1;
    float* x1  = g_f + O_X1;
    float* cqp = g_f + O_CQP;
    float* cab = g_f + O_CAB;
    float* p2  = g_f + O_P2;
    float* x2  = g_f + O_X2;
    float* w1p = g_f + O_W1P;
    float* act = g_f + O_ACT;
    float* w2p = g_f + O_W2P;
    float* kc  = g_f + O_KC;
    float* vc  = g_f + O_VC;

    // ---- init ----
    for (int i = gid; i < 49152; i += gsz) wz[i] = z_w[i >> 7] * z_seq[i];
    for (int i = gid; i < OUT_HID; i += gsz) out[i] = 0.f;
    for (int i = gid; i < MAXTOK * 128; i += gsz) g_amax[i] = 0ull;
    for (int i = tid; i < 384; i += NTHR) s_act[i] = (z_w[i] > 0.01f) ? 1 : 0;
    if (tid < 128) {
        s_pos[tid] = 0; s_tip[tid] = 0; s_phr[tid] = 0;
        int a0 = (z_w[tid * 3] > 0.01f) ? 1 : 0;
        s_done[tid] = !a0;
        s_nxt[tid]  = BOSTOK;
        s_gate[tid] = a0 ? 1.f : 0.f;
    }
    gsync();

    // ---- memories = wz[384,128] @ Wl2d[128,4096] : 192 tiles ----
    for (int tile = bx; tile < 192; tile += NBLK) {
        int by = tile >> 6, cx = tile & 63;
        run_tile64(wz + (size_t)by * 128 * 128, nullptr, 128, Wl2d, 4096, cx * 64,
                   0, 128, sA, sW, acc);
        store_tile64(mem + (size_t)by * 128 * 4096, 4096, cx * 64, acc);
    }
    gsync();

    // ---- ck/cv = mem[3072,512] @ Wck/Wcv : 384 tiles ----
    for (int tile = bx; tile < 384; tile += NBLK) {
        int isv = tile >= 192;
        int idx = isv ? tile - 192 : tile;
        int by = idx >> 3, cx = idx & 7;
        run_tile64(mem + (size_t)by * 65536, nullptr, 512, isv ? Wcv : Wck, 512, cx * 64,
                   0, 512, sA, sW, acc);
        store_tile64((isv ? cvb : ckb) + (size_t)by * 65536, 512, cx * 64, acc);
    }
    gsync();

    // ================= decode loop =================
    for (int t = 0; t < MAXTOK; t++) {
        // ---- QKV: splitK4 (chunk 128), 96 tiles ----
        for (int tile = bx; tile < 96; tile += NBLK) {
            int sel = tile >> 5, rem = tile & 31;
            int ks = rem >> 3, cx = rem & 7;
            const float* W_ = (sel == 0) ? Wq : ((sel == 1) ? Wk : Wv);
            float* C_ = (sel == 0) ? qp : ((sel == 1) ? kp : vp);
            run_tile64(temb, s_nxt, 512, W_, 512, cx * 64, ks * 128, 128, sA, sW, acc);
            store_tile64(C_ + ks * 65536, 512, cx * 64, acc);
        }
        gsync();

        // ---- attention ----
        {
            int wid = tid >> 5, lane = tid & 31;
            int gw = bx * 8 + wid;
            if (gw < 1024) {
                int b = gw >> 3, h = gw & 7;
                int off = b * 512 + h * 64 + lane * 2;
                float2 qv = make_float2(0.f, 0.f), kv2 = qv, vv2 = qv;
#pragma unroll
                for (int j = 0; j < 4; j++) {
                    float2 a = *(const float2*)(qp + j * 65536 + off);
                    float2 c = *(const float2*)(kp + j * 65536 + off);
                    float2 d = *(const float2*)(vp + j * 65536 + off);
                    qv.x += a.x; qv.y += a.y;
                    kv2.x += c.x; kv2.y += c.y;
                    vv2.x += d.x; vv2.y += d.y;
                }
                float* krow = kc + (size_t)(b * 8 + h) * CTOK * 64;
                float* vrow = vc + (size_t)(b * 8 + h) * CTOK * 64;
                *(float2*)(krow + (size_t)t * 64 + lane * 2) = kv2;
                *(float2*)(vrow + (size_t)t * 64 + lane * 2) = vv2;
                float* sqw = s_q + wid * 64;
                float* scw = s_sc + wid * 152;
                *(float2*)(sqw + lane * 2) = qv;
                __syncwarp();
                for (int s = lane; s < t; s += 32) {
                    const float* kr = krow + (size_t)s * 64;
                    float d = 0.f;
#pragma unroll
                    for (int c = 0; c < 16; c++) {
                        float4 kv = *(const float4*)(kr + c * 4);
                        float4 qq = *(const float4*)(sqw + c * 4);
                        d += kv.x * qq.x + kv.y * qq.y + kv.z * qq.z + kv.w * qq.w;
                    }
                    scw[s] = d * 0.125f;
                }
                float pt = wred(qv.x * kv2.x + qv.y * kv2.y) * 0.125f;
                if (lane == 0) scw[t] = pt;
                __syncwarp();
                int n = t + 1;
                float mx = -1e30f;
                for (int s = lane; s < n; s += 32) mx = fmaxf(mx, scw[s]);
                for (int o = 16; o; o >>= 1) mx = fmaxf(mx, __shfl_xor_sync(0xffffffffu, mx, o));
                float sum = 0.f;
                for (int s = lane; s < n; s += 32) {
                    float e = expf(scw[s] - mx);
                    scw[s] = e;
                    sum += e;
                }
                for (int o = 16; o; o >>= 1) sum += __shfl_xor_sync(0xffffffffu, sum, o);
                float inv = 1.0f / sum;
                __syncwarp();
                float a0 = 0.f, a1 = 0.f;
                for (int s = 0; s < t; s++) {
                    float p = scw[s] * inv;
                    float2 vv = *(const float2*)(vrow + (size_t)s * 64 + lane * 2);
                    a0 += p * vv.x;
                    a1 += p * vv.y;
                }
                float ptn = scw[t] * inv;
                a0 += ptn * vv2.x;
                a1 += ptn * vv2.y;
                *(float2*)(sab + off) = make_float2(a0, a1);
            }
        }
        gsync();

        // ---- Wo: splitK16 (chunk 32), 128 tiles ----
        for (int tile = bx; tile < 128; tile += NBLK) {
            int cx = tile & 7, ks = tile >> 3;
            run_tile64(sab, nullptr, 512, Wo, 512, cx * 64, ks * 32, 32, sA, sW, acc);
            store_tile64(p1 + ks * 65536, 512, cx * 64, acc);
        }
        gsync();

        // ---- x1 = temb[nxt] + sum16(p1) ----
        for (int i = gid; i < 65536; i += gsz)
            x1[i] = temb[(size_t)s_nxt[i >> 9] * 512 + (i & 511)] + sum16(p1, i);
        gsync();

        // ---- cq: splitK16, 128 tiles ----
        for (int tile = bx; tile < 128; tile += NBLK) {
            int cx = tile & 7, ks = tile >> 3;
            run_tile64(x1, nullptr, 512, Wcq, 512, cx * 64, ks * 32, 32, sA, sW, acc);
            store_tile64(cqp + ks * 65536, 512, cx * 64, acc);
        }
        gsync();

        // ---- cross-attention ----
        {
            int wid = tid >> 5, lane = tid & 31;
            int gw = bx * 8 + wid;
            if (gw < 1024) {
                int b = gw >> 3, h = gw & 7;
                int off = b * 512 + h * 64 + lane * 2;
                float qx = 0.f, qy = 0.f;
#pragma unroll
                for (int j = 0; j < 16; j++) {
                    float2 p = *(const float2*)(cqp + j * 65536 + off);
                    qx += p.x; qy += p.y;
                }
                int phr = s_phr[b];
                int i = phr < 2 ? phr : 2;
                float g = s_gate[b];
                size_t base = (size_t)((b * 3 + i) * 8) * 512 + h * 64 + lane * 2;
                const float* Kp = ckb + base;
                const float* Vp = cvb + base;
                float s[8], mx = -1e30f;
#pragma unroll
                for (int m = 0; m < 8; m++) {
                    float2 kv = *(const float2*)(Kp + m * 512);
                    s[m] = wred(qx * kv.x + qy * kv.y) * 0.125f;
                    mx = fmaxf(mx, s[m]);
                }
                float sum = 0.f;
#pragma unroll
                for (int m = 0; m < 8; m++) { s[m] = expf(s[m] - mx); sum += s[m]; }
                float inv = 1.0f / sum;
                float a0 = 0.f, a1 = 0.f;
#pragma unroll
                for (int m = 0; m < 8; m++) {
                    float2 vv = *(const float2*)(Vp + m * 512);
                    a0 += s[m] * vv.x;
                    a1 += s[m] * vv.y;
                }
                *(float2*)(cab + off) = make_float2(a0 * inv * g, a1 * inv * g);
            }
        }
        gsync();

        // ---- Wco: splitK16, 128 tiles ----
        for (int tile = bx; tile < 128; tile += NBLK) {
            int cx = tile & 7, ks = tile >> 3;
            run_tile64(cab, nullptr, 512, Wco, 512, cx * 64, ks * 32, 32, sA, sW, acc);
            store_tile64(p2 + ks * 65536, 512, cx * 64, acc);
        }
        gsync();

        // ---- x2 = x1 + sum16(p2) ----
        for (int i = gid; i < 65536; i += gsz)
            x2[i] = x1[i] + sum16(p2, i);
        gsync();

        // ---- W1: splitK4 (chunk 128), 128 tiles ----
        for (int tile = bx; tile < 128; tile += NBLK) {
            int cx = tile & 31, ks = tile >> 5;
            run_tile64(x2, nullptr, 512, W1, 2048, cx * 64, ks * 128, 128, sA, sW, acc);
            store_tile64(w1p + ks * 262144, 2048, cx * 64, acc);
        }
        gsync();

        // ---- act = gelu(sum4(w1p)) ----
        for (int i = gid; i < 262144; i += gsz)
            act[i] = gelu_tanh((w1p[i] + w1p[262144 + i]) + (w1p[524288 + i] + w1p[786432 + i]));
        gsync();

        // ---- W2: splitK16 (chunk 128), 128 tiles ----
        for (int tile = bx; tile < 128; tile += NBLK) {
            int cx = tile & 7, ks = tile >> 3;
            run_tile64(act, nullptr, 2048, W2, 512, cx * 64, ks * 128, 128, sA, sW, acc);
            store_tile64(w2p + ks * 65536, 512, cx * 64, acc);
        }
        gsync();

        // ---- hid = x2 + sum16(w2p) -> out ----
        float* hid = out + OUT_HID + (size_t)t * 65536;
        for (int i = gid; i < 65536; i += gsz)
            hid[i] = x2[i] + sum16(w2p, i);
        gsync();

        // ---- logits + fused argmax: 125 tiles, full K ----
        for (int tile = bx; tile < 125; tile += NBLK) {
            run_tile64(hid, nullptr, 512, Wout, VOC, tile * 64, 0, 512, sA, sW, acc);
            const int rg4 = (tid >> 3) << 2, cg8 = (tid & 7) << 3;
#pragma unroll
            for (int i = 0; i < 4; i++) {
                int row = rg4 + i;
                unsigned long long best = 0ull;
#pragma unroll
                for (int j = 0; j < 8; j++) {
                    int col = tile * 64 + cg8 + j;
                    unsigned u = __float_as_uint(acc[i][j]);
                    u = (u & 0x80000000u) ? ~u : (u | 0x80000000u);
                    best = umax64(best, ((unsigned long long)u << 32) |
                                        (unsigned)(VOC - 1 - col));
                }
                best = umax64(best, __shfl_xor_sync(0xffffffffu, best, 1));
                best = umax64(best, __shfl_xor_sync(0xffffffffu, best, 2));
                best = umax64(best, __shfl_xor_sync(0xffffffffu, best, 4));
                if ((tid & 7) == 0) atomicMax(&g_amax[t * 128 + row], best);
            }
        }
        gsync();

        // ---- state machine (replicated per block; block 0 writes outputs) ----
        if (tid < 128) {
            int b = tid;
            unsigned long long key = g_amax[t * 128 + b];
            int col = (VOC - 1) - (int)(key & 0xffffffffu);
            int pos = s_pos[b], tip = s_tip[b], phr = s_phr[b], done = s_done[b];
            int live = !done;
            if (live && bx == 0) {
                out[b * MAXTOK + pos] = (float)col;
                out[OUT_GENM + b * MAXTOK + pos] = 1.0f;
            }
            pos += live;
            tip += live;
            int eos = (col == EOSTOK) && (tip >= 1);
            int sw = (eos || (tip >= MAXPER)) && live;
            phr += sw;
            if (sw) tip = 0;
            int cp = phr < 2 ? phr : 2;
            if (sw && phr < KPH && bx == 0) out[OUT_BOUNDS + b * 3 + cp] = (float)pos;
            done = done || (phr >= KPH) || (sw && !s_act[b * 3 + cp]);
            s_pos[b] = pos;
            s_tip[b] = tip;
            s_phr[b] = phr;
            s_done[b] = done;
            s_nxt[b] = col;
            s_gate[b] = (s_act[b * 3 + cp] && !done) ? 1.0f : 0.0f;
        }
        __syncthreads();
    }
}

// ---------------- host ----------------
extern "C" void kernel_launch(void* const* d_in, const int* in_sizes, int n_in,
                              void* d_out, int out_size)
{
    (void)in_sizes; (void)n_in; (void)out_size;
    mega_kernel<<<NBLK, NTHR>>>(
        (const float*)d_in[0],  (const float*)d_in[1],  (const float*)d_in[2],
        (const float*)d_in[3],  (const float*)d_in[4],  (const float*)d_in[5],
        (const float*)d_in[6],  (const float*)d_in[7],  (const float*)d_in[8],
        (const float*)d_in[9],  (const float*)d_in[10], (const float*)d_in[11],
        (const float*)d_in[12], (const float*)d_in[13], (const float*)d_in[14],
        (float*)d_out);
}

// round 9
// speedup vs baseline: 1.0329x; 1.0329x over previous
#include <cuda_runtime.h>
#include <cuda_bf16.h>
#include <cstdint>

// ---------------- constants ----------------
#define NBLK   148
#define NTHR   256
#define KPH    3
#define MAXPER 48
#define MAXTOK 144
#define CTOK   145
#define HD     512
#define VOC    8000
#define BOSTOK 1
#define EOSTOK 2

// ---------------- scratch offsets (floats) ----------------
#define O_WZ    0u
#define O_MEM   49152u
#define O_CK    1622016u
#define O_CV    3194880u
#define O_QP    4767744u
#define O_KP    5029888u
#define O_VP    5292032u
#define O_SAB   5554176u
#define O_P1    5619712u
#define O_X1    6668288u
#define O_CQP   6733824u
#define O_CAB   7782400u
#define O_P2    7847936u
#define O_X2    8896512u
#define O_W1P   8962048u
#define O_ACT   10010624u
#define O_W2P   10272768u
#define O_KC    11321344u
#define O_VC    20824064u
#define O_HIDB  30326784u   /* hid hi/mid/lo bf16: 3*65536 bf16 = 98304 floats */
#define O_WBF   30425088u   /* Wout hi/mid/lo bf16: 3*4096000 bf16 = 6144000 floats */
#define F_TOTAL 36569088u

// d_out: tokens[128*144] | genm[128*144] | bounds[128*3] | hiddens[144*128*512]
#define OUT_GENM   18432
#define OUT_BOUNDS 36864
#define OUT_HID    37248

__device__ static __align__(128) float g_f[F_TOTAL];
__device__ static unsigned long long g_amax[MAXTOK * 128];
__device__ static unsigned g_count;
__device__ static volatile unsigned g_gen;

// ---------------- helpers ----------------
__device__ __forceinline__ float gelu_tanh(float x) {
    float x3 = x * x * x;
    return 0.5f * x * (1.0f + tanhf(0.7978845608028654f * (x + 0.044715f * x3)));
}
__device__ __forceinline__ float wred(float p) {
    p += __shfl_xor_sync(0xffffffffu, p, 16);
    p += __shfl_xor_sync(0xffffffffu, p, 8);
    p += __shfl_xor_sync(0xffffffffu, p, 4);
    p += __shfl_xor_sync(0xffffffffu, p, 2);
    p += __shfl_xor_sync(0xffffffffu, p, 1);
    return p;
}
__device__ __forceinline__ unsigned long long umax64(unsigned long long a, unsigned long long b) {
    return a > b ? a : b;
}

__device__ __forceinline__ void gsync() {
    __syncthreads();
    if (threadIdx.x == 0) {
        unsigned gen = g_gen;
        __threadfence();
        if (atomicAdd(&g_count, 1u) == (unsigned)(NBLK - 1)) {
            g_count = 0u;
            __threadfence();
            g_gen = gen + 1u;
        } else {
            while (g_gen == gen) __nanosleep(64);
        }
        __threadfence();
    }
    __syncthreads();
}

// bf16 mma.sync m16n8k16 (base-target instruction; runs on tensor pipe as HMMA)
__device__ __forceinline__ void mma_bf16(float acc[4],
                                         unsigned a0, unsigned a1, unsigned a2, unsigned a3,
                                         unsigned b0, unsigned b1)
{
    asm volatile("mma.sync.aligned.m16n8k16.row.col.f32.bf16.bf16.f32 "
                 "{%0,%1,%2,%3}, {%4,%5,%6,%7}, {%8,%9}, {%0,%1,%2,%3};"
                 : "+f"(acc[0]), "+f"(acc[1]), "+f"(acc[2]), "+f"(acc[3])
                 : "r"(a0), "r"(a1), "r"(a2), "r"(a3), "r"(b0), "r"(b1));
}

// ---------------- 128x64 FFMA tile core (non-logits GEMMs) ----------------
__device__ __forceinline__ void run_tile64(
    const float* __restrict__ A, const int* gidx, int lda,
    const float* __restrict__ W, int ldw, int wcol,
    int kOff, int kChunk, float* sA, float* sW, float acc[4][8])
{
    const int tid  = threadIdx.x;
    const int arow = tid >> 3, ak4 = (tid & 7) << 2;
    const int wn8  = (tid & 7) << 3;
    const int rg4  = (tid >> 3) << 2, cg8 = (tid & 7) << 3;

    const float* Arow[4];
#pragma unroll
    for (int i = 0; i < 4; i++) {
        int r = arow + (i << 5);
        int rr = gidx ? gidx[r] : r;
        Arow[i] = A + (size_t)rr * lda + kOff + ak4;
    }
    const float* Wp = W + (size_t)(kOff + arow) * ldw + wcol + wn8;

#pragma unroll
    for (int i = 0; i < 4; i++)
#pragma unroll
        for (int j = 0; j < 8; j++) acc[i][j] = 0.f;

    float4 pa0 = *(const float4*)(Arow[0]);
    float4 pa1 = *(const float4*)(Arow[1]);
    float4 pa2 = *(const float4*)(Arow[2]);
    float4 pa3 = *(const float4*)(Arow[3]);
    float4 pw0 = *(const float4*)(Wp);
    float4 pw1 = *(const float4*)(Wp + 4);

    for (int kt = 0; kt < kChunk; kt += 32) {
        sA[(ak4 + 0) * 132 + arow      ] = pa0.x;
        sA[(ak4 + 1) * 132 + arow      ] = pa0.y;
        sA[(ak4 + 2) * 132 + arow      ] = pa0.z;
        sA[(ak4 + 3) * 132 + arow      ] = pa0.w;
        sA[(ak4 + 0) * 132 + arow + 32 ] = pa1.x;
        sA[(ak4 + 1) * 132 + arow + 32 ] = pa1.y;
        sA[(ak4 + 2) * 132 + arow + 32 ] = pa1.z;
        sA[(ak4 + 3) * 132 + arow + 32 ] = pa1.w;
        sA[(ak4 + 0) * 132 + arow + 64 ] = pa2.x;
        sA[(ak4 + 1) * 132 + arow + 64 ] = pa2.y;
        sA[(ak4 + 2) * 132 + arow + 64 ] = pa2.z;
        sA[(ak4 + 3) * 132 + arow + 64 ] = pa2.w;
        sA[(ak4 + 0) * 132 + arow + 96 ] = pa3.x;
        sA[(ak4 + 1) * 132 + arow + 96 ] = pa3.y;
        sA[(ak4 + 2) * 132 + arow + 96 ] = pa3.z;
        sA[(ak4 + 3) * 132 + arow + 96 ] = pa3.w;
        *(float4*)&sW[arow * 64 + wn8    ] = pw0;
        *(float4*)&sW[arow * 64 + wn8 + 4] = pw1;
        __syncthreads();

        if (kt + 32 < kChunk) {
            pa0 = *(const float4*)(Arow[0] + kt + 32);
            pa1 = *(const float4*)(Arow[1] + kt + 32);
            pa2 = *(const float4*)(Arow[2] + kt + 32);
            pa3 = *(const float4*)(Arow[3] + kt + 32);
            pw0 = *(const float4*)(Wp + (size_t)(kt + 32) * ldw);
            pw1 = *(const float4*)(Wp + (size_t)(kt + 32) * ldw + 4);
        }

#pragma unroll
        for (int kk = 0; kk < 32; kk++) {
            float4 av  = *(const float4*)&sA[kk * 132 + rg4];
            float4 w0v = *(const float4*)&sW[kk * 64 + cg8];
            float4 w1v = *(const float4*)&sW[kk * 64 + cg8 + 4];
            acc[0][0] += av.x * w0v.x; acc[0][1] += av.x * w0v.y; acc[0][2] += av.x * w0v.z; acc[0][3] += av.x * w0v.w;
            acc[0][4] += av.x * w1v.x; acc[0][5] += av.x * w1v.y; acc[0][6] += av.x * w1v.z; acc[0][7] += av.x * w1v.w;
            acc[1][0] += av.y * w0v.x; acc[1][1] += av.y * w0v.y; acc[1][2] += av.y * w0v.z; acc[1][3] += av.y * w0v.w;
            acc[1][4] += av.y * w1v.x; acc[1][5] += av.y * w1v.y; acc[1][6] += av.y * w1v.z; acc[1][7] += av.y * w1v.w;
            acc[2][0] += av.z * w0v.x; acc[2][1] += av.z * w0v.y; acc[2][2] += av.z * w0v.z; acc[2][3] += av.z * w0v.w;
            acc[2][4] += av.z * w1v.x; acc[2][5] += av.z * w1v.y; acc[2][6] += av.z * w1v.z; acc[2][7] += av.z * w1v.w;
            acc[3][0] += av.w * w0v.x; acc[3][1] += av.w * w0v.y; acc[3][2] += av.w * w0v.z; acc[3][3] += av.w * w0v.w;
            acc[3][4] += av.w * w1v.x; acc[3][5] += av.w * w1v.y; acc[3][6] += av.w * w1v.z; acc[3][7] += av.w * w1v.w;
        }
        __syncthreads();
    }
}

__device__ __forceinline__ void store_tile64(float* __restrict__ C, int ldc, int colBase,
                                             const float acc[4][8])
{
    const int rg4 = (threadIdx.x >> 3) << 2, cg8 = (threadIdx.x & 7) << 3;
#pragma unroll
    for (int i = 0; i < 4; i++) {
        float* p = C + (size_t)(rg4 + i) * ldc + colBase + cg8;
        *(float4*)p       = make_float4(acc[i][0], acc[i][1], acc[i][2], acc[i][3]);
        *(float4*)(p + 4) = make_float4(acc[i][4], acc[i][5], acc[i][6], acc[i][7]);
    }
}

__device__ __forceinline__ float sum16(const float* p, int i) {
    float a = (p[i] + p[65536 + i]) + (p[131072 + i] + p[196608 + i]);
    float b = (p[262144 + i] + p[327680 + i]) + (p[393216 + i] + p[458752 + i]);
    float c = (p[524288 + i] + p[589824 + i]) + (p[655360 + i] + p[720896 + i]);
    float d = (p[786432 + i] + p[851968 + i]) + (p[917504 + i] + p[983040 + i]);
    return (a + b) + (c + d);
}

// ---------------- persistent mega-kernel ----------------
__global__ void __launch_bounds__(NTHR, 1) mega_kernel(
    const float* __restrict__ z_seq, const float* __restrict__ z_w,
    const float* __restrict__ Wl2d, const float* __restrict__ temb,
    const float* __restrict__ Wq,  const float* __restrict__ Wk,
    const float* __restrict__ Wv,  const float* __restrict__ Wo,
    const float* __restrict__ Wcq, const float* __restrict__ Wck,
    const float* __restrict__ Wcv, const float* __restrict__ Wco,
    const float* __restrict__ W1,  const float* __restrict__ W2,
    const float* __restrict__ Wout, float* __restrict__ out)
{
    __shared__ float sA[32 * 132];
    __shared__ float sW[32 * 64];
    __shared__ float s_q[8 * 64];
    __shared__ float s_sc[8 * 152];
    __shared__ int   s_act[384];
    __shared__ int   s_pos[128], s_tip[128], s_phr[128], s_done[128], s_nxt[128];
    __shared__ float s_gate[128];
    extern __shared__ __align__(16) char dsm[];

    // dynamic smem: A splits (128x64 bf16, pitch 72) + B splits (64x64 bf16, pitch 72)
    __nv_bfloat16* sAH = (__nv_bfloat16*)dsm;            // 18432 B
    __nv_bfloat16* sAM = sAH + 9216;
    __nv_bfloat16* sAL = sAM + 9216;
    __nv_bfloat16* sBH = sAL + 9216;                     // 9216 B each
    __nv_bfloat16* sBM = sBH + 4608;
    __nv_bfloat16* sBL = sBM + 4608;

    const int tid = threadIdx.x;
    const int bx  = blockIdx.x;
    const int gid = bx * NTHR + tid;
    const int gsz = NBLK * NTHR;
    float acc[4][8];

    float* wz  = g_f + O_WZ;
    float* mem = g_f + O_MEM;
    float* ckb = g_f + O_CK;
    float* cvb = g_f + O_CV;
    float* qp  = g_f + O_QP;
    float* kp  = g_f + O_KP;
    float* vp  = g_f + O_VP;
    float* sab = g_f + O_SAB;
    float* p1  = g_f + O_P1;
    float* x1  = g_f + O_X1;
    float* cqp = g_f + O_CQP;
    float* cab = g_f + O_CAB;
    float* p2  = g_f + O_P2;
    float* x2  = g_f + O_X2;
    float* w1p = g_f + O_W1P;
    float* act = g_f + O_ACT;
    float* w2p = g_f + O_W2P;
    float* kc  = g_f + O_KC;
    float* vc  = g_f + O_VC;
    __nv_bfloat16* hidH = (__nv_bfloat16*)(g_f + O_HIDB);
    __nv_bfloat16* hidM = hidH + 65536;
    __nv_bfloat16* hidL = hidM + 65536;
    __nv_bfloat16* wbH  = (__nv_bfloat16*)(g_f + O_WBF);
    __nv_bfloat16* wbM  = wbH + 4096000;
    __nv_bfloat16* wbL  = wbM + 4096000;

    // ---- init ----
    for (int i = gid; i < 49152; i += gsz) wz[i] = z_w[i >> 7] * z_seq[i];
    for (int i = gid; i < OUT_HID; i += gsz) out[i] = 0.f;
    for (int i = gid; i < MAXTOK * 128; i += gsz) g_amax[i] = 0ull;
    // split Wout[k,8000] into bf16 hi/mid/lo, laid out [n][k] (K-major rows = col-major B)
    for (int i = gid; i < 4096000; i += gsz) {
        int n = i >> 9, k = i & 511;
        float v = Wout[(size_t)k * VOC + n];
        __nv_bfloat16 h = __float2bfloat16(v);
        float r = v - __bfloat162float(h);
        __nv_bfloat16 m = __float2bfloat16(r);
        float r2 = r - __bfloat162float(m);
        wbH[i] = h; wbM[i] = m; wbL[i] = __float2bfloat16(r2);
    }
    for (int i = tid; i < 384; i += NTHR) s_act[i] = (z_w[i] > 0.01f) ? 1 : 0;
    if (tid < 128) {
        s_pos[tid] = 0; s_tip[tid] = 0; s_phr[tid] = 0;
        int a0 = (z_w[tid * 3] > 0.01f) ? 1 : 0;
        s_done[tid] = !a0;
        s_nxt[tid]  = BOSTOK;
        s_gate[tid] = a0 ? 1.f : 0.f;
    }
    gsync();

    // ---- memories = wz[384,128] @ Wl2d[128,4096] : 192 tiles ----
    for (int tile = bx; tile < 192; tile += NBLK) {
        int by = tile >> 6, cx = tile & 63;
        run_tile64(wz + (size_t)by * 128 * 128, nullptr, 128, Wl2d, 4096, cx * 64,
                   0, 128, sA, sW, acc);
        store_tile64(mem + (size_t)by * 128 * 4096, 4096, cx * 64, acc);
    }
    gsync();

    // ---- ck/cv = mem[3072,512] @ Wck/Wcv : 384 tiles ----
    for (int tile = bx; tile < 384; tile += NBLK) {
        int isv = tile >= 192;
        int idx = isv ? tile - 192 : tile;
        int by = idx >> 3, cx = idx & 7;
        run_tile64(mem + (size_t)by * 65536, nullptr, 512, isv ? Wcv : Wck, 512, cx * 64,
                   0, 512, sA, sW, acc);
        store_tile64((isv ? cvb : ckb) + (size_t)by * 65536, 512, cx * 64, acc);
    }
    gsync();

    // ================= decode loop =================
    for (int t = 0; t < MAXTOK; t++) {
        // ---- QKV: splitK4 (chunk 128), 96 tiles ----
        for (int tile = bx; tile < 96; tile += NBLK) {
            int sel = tile >> 5, rem = tile & 31;
            int ks = rem >> 3, cx = rem & 7;
            const float* W_ = (sel == 0) ? Wq : ((sel == 1) ? Wk : Wv);
            float* C_ = (sel == 0) ? qp : ((sel == 1) ? kp : vp);
            run_tile64(temb, s_nxt, 512, W_, 512, cx * 64, ks * 128, 128, sA, sW, acc);
            store_tile64(C_ + ks * 65536, 512, cx * 64, acc);
        }
        gsync();

        // ---- attention ----
        {
            int wid = tid >> 5, lane = tid & 31;
            int gw = bx * 8 + wid;
            if (gw < 1024) {
                int b = gw >> 3, h = gw & 7;
                int off = b * 512 + h * 64 + lane * 2;
                float2 qv = make_float2(0.f, 0.f), kv2 = qv, vv2 = qv;
#pragma unroll
                for (int j = 0; j < 4; j++) {
                    float2 a = *(const float2*)(qp + j * 65536 + off);
                    float2 c = *(const float2*)(kp + j * 65536 + off);
                    float2 d = *(const float2*)(vp + j * 65536 + off);
                    qv.x += a.x; qv.y += a.y;
                    kv2.x += c.x; kv2.y += c.y;
                    vv2.x += d.x; vv2.y += d.y;
                }
                float* krow = kc + (size_t)(b * 8 + h) * CTOK * 64;
                float* vrow = vc + (size_t)(b * 8 + h) * CTOK * 64;
                *(float2*)(krow + (size_t)t * 64 + lane * 2) = kv2;
                *(float2*)(vrow + (size_t)t * 64 + lane * 2) = vv2;
                float* sqw = s_q + wid * 64;
                float* scw = s_sc + wid * 152;
                *(float2*)(sqw + lane * 2) = qv;
                __syncwarp();
                for (int s = lane; s < t; s += 32) {
                    const float* kr = krow + (size_t)s * 64;
                    float d = 0.f;
#pragma unroll
                    for (int c = 0; c < 16; c++) {
                        float4 kv = *(const float4*)(kr + c * 4);
                        float4 qq = *(const float4*)(sqw + c * 4);
                        d += kv.x * qq.x + kv.y * qq.y + kv.z * qq.z + kv.w * qq.w;
                    }
                    scw[s] = d * 0.125f;
                }
                float pt = wred(qv.x * kv2.x + qv.y * kv2.y) * 0.125f;
                if (lane == 0) scw[t] = pt;
                __syncwarp();
                int n = t + 1;
                float mx = -1e30f;
                for (int s = lane; s < n; s += 32) mx = fmaxf(mx, scw[s]);
                for (int o = 16; o; o >>= 1) mx = fmaxf(mx, __shfl_xor_sync(0xffffffffu, mx, o));
                float sum = 0.f;
                for (int s = lane; s < n; s += 32) {
                    float e = expf(scw[s] - mx);
                    scw[s] = e;
                    sum += e;
                }
                for (int o = 16; o; o >>= 1) sum += __shfl_xor_sync(0xffffffffu, sum, o);
                float inv = 1.0f / sum;
                __syncwarp();
                float a0 = 0.f, a1 = 0.f;
                for (int s = 0; s < t; s++) {
                    float p = scw[s] * inv;
                    float2 vv = *(const float2*)(vrow + (size_t)s * 64 + lane * 2);
                    a0 += p * vv.x;
                    a1 += p * vv.y;
                }
                float ptn = scw[t] * inv;
                a0 += ptn * vv2.x;
                a1 += ptn * vv2.y;
                *(float2*)(sab + off) = make_float2(a0, a1);
            }
        }
        gsync();

        // ---- Wo: splitK16 (chunk 32), 128 tiles ----
        for (int tile = bx; tile < 128; tile += NBLK) {
            int cx = tile & 7, ks = tile >> 3;
            run_tile64(sab, nullptr, 512, Wo, 512, cx * 64, ks * 32, 32, sA, sW, acc);
            store_tile64(p1 + ks * 65536, 512, cx * 64, acc);
        }
        gsync();

        // ---- x1 = temb[nxt] + sum16(p1) ----
        for (int i = gid; i < 65536; i += gsz)
            x1[i] = temb[(size_t)s_nxt[i >> 9] * 512 + (i & 511)] + sum16(p1, i);
        gsync();

        // ---- cq: splitK16, 128 tiles ----
        for (int tile = bx; tile < 128; tile += NBLK) {
            int cx = tile & 7, ks = tile >> 3;
            run_tile64(x1, nullptr, 512, Wcq, 512, cx * 64, ks * 32, 32, sA, sW, acc);
            store_tile64(cqp + ks * 65536, 512, cx * 64, acc);
        }
        gsync();

        // ---- cross-attention ----
        {
            int wid = tid >> 5, lane = tid & 31;
            int gw = bx * 8 + wid;
            if (gw < 1024) {
                int b = gw >> 3, h = gw & 7;
                int off = b * 512 + h * 64 + lane * 2;
                float qx = 0.f, qy = 0.f;
#pragma unroll
                for (int j = 0; j < 16; j++) {
                    float2 p = *(const float2*)(cqp + j * 65536 + off);
                    qx += p.x; qy += p.y;
                }
                int phr = s_phr[b];
                int i = phr < 2 ? phr : 2;
                float g = s_gate[b];
                size_t base = (size_t)((b * 3 + i) * 8) * 512 + h * 64 + lane * 2;
                const float* Kp = ckb + base;
                const float* Vp = cvb + base;
                float s[8], mx = -1e30f;
#pragma unroll
                for (int m = 0; m < 8; m++) {
                    float2 kv = *(const float2*)(Kp + m * 512);
                    s[m] = wred(qx * kv.x + qy * kv.y) * 0.125f;
                    mx = fmaxf(mx, s[m]);
                }
                float sum = 0.f;
#pragma unroll
                for (int m = 0; m < 8; m++) { s[m] = expf(s[m] - mx); sum += s[m]; }
                float inv = 1.0f / sum;
                float a0 = 0.f, a1 = 0.f;
#pragma unroll
                for (int m = 0; m < 8; m++) {
                    float2 vv = *(const float2*)(Vp + m * 512);
                    a0 += s[m] * vv.x;
                    a1 += s[m] * vv.y;
                }
                *(float2*)(cab + off) = make_float2(a0 * inv * g, a1 * inv * g);
            }
        }
        gsync();

        // ---- Wco: splitK16, 128 tiles ----
        for (int tile = bx; tile < 128; tile += NBLK) {
            int cx = tile & 7, ks = tile >> 3;
            run_tile64(cab, nullptr, 512, Wco, 512, cx * 64, ks * 32, 32, sA, sW, acc);
            store_tile64(p2 + ks * 65536, 512, cx * 64, acc);
        }
        gsync();

        // ---- x2 = x1 + sum16(p2) ----
        for (int i = gid; i < 65536; i += gsz)
            x2[i] = x1[i] + sum16(p2, i);
        gsync();

        // ---- W1: splitK4 (chunk 128), 128 tiles ----
        for (int tile = bx; tile < 128; tile += NBLK) {
            int cx = tile & 31, ks = tile >> 5;
            run_tile64(x2, nullptr, 512, W1, 2048, cx * 64, ks * 128, 128, sA, sW, acc);
            store_tile64(w1p + ks * 262144, 2048, cx * 64, acc);
        }
        gsync();

        // ---- act = gelu(sum4(w1p)) ----
        for (int i = gid; i < 262144; i += gsz)
            act[i] = gelu_tanh((w1p[i] + w1p[262144 + i]) + (w1p[524288 + i] + w1p[786432 + i]));
        gsync();

        // ---- W2: splitK16 (chunk 128), 128 tiles ----
        for (int tile = bx; tile < 128; tile += NBLK) {
            int cx = tile & 7, ks = tile >> 3;
            run_tile64(act, nullptr, 2048, W2, 512, cx * 64, ks * 128, 128, sA, sW, acc);
            store_tile64(w2p + ks * 65536, 512, cx * 64, acc);
        }
        gsync();

        // ---- hid = x2 + sum16(w2p) -> out, fused hi/mid/lo bf16 split ----
        float* hid = out + OUT_HID + (size_t)t * 65536;
        for (int i = gid; i < 65536; i += gsz) {
            float v = x2[i] + sum16(w2p, i);
            hid[i] = v;
            __nv_bfloat16 h = __float2bfloat16(v);
            float r = v - __bfloat162float(h);
            __nv_bfloat16 m = __float2bfloat16(r);
            hidH[i] = h; hidM[i] = m;
            hidL[i] = __float2bfloat16(r - __bfloat162float(m));
        }
        gsync();

        // ---- logits via mma.sync bf16x6 emulated fp32 + fused argmax ----
        if (bx < 125) {
            const int n0 = bx * 64;
            const int w = tid >> 5, lane = tid & 31;
            const int g = lane >> 2, tg = lane & 3;
            float la[8][4];
#pragma unroll
            for (int nt = 0; nt < 8; nt++)
#pragma unroll
                for (int j = 0; j < 4; j++) la[nt][j] = 0.f;

            for (int kchunk = 0; kchunk < 8; kchunk++) {
                // stage A chunk [128 x 64] x3 splits (pitch 72)
                for (int i = tid; i < 1024; i += NTHR) {
                    int row = i >> 3, c8 = (i & 7) << 3;
                    size_t src = (size_t)row * 512 + (kchunk << 6) + c8;
                    int dst = row * 72 + c8;
                    *(uint4*)(sAH + dst) = *(const uint4*)(hidH + src);
                    *(uint4*)(sAM + dst) = *(const uint4*)(hidM + src);
                    *(uint4*)(sAL + dst) = *(const uint4*)(hidL + src);
                }
                // stage B chunk [64n x 64k] x3 splits (pitch 72)
                for (int i = tid; i < 512; i += NTHR) {
                    int row = i >> 3, c8 = (i & 7) << 3;
                    size_t src = (size_t)(n0 + row) * 512 + (kchunk << 6) + c8;
                    int dst = row * 72 + c8;
                    *(uint4*)(sBH + dst) = *(const uint4*)(wbH + src);
                    *(uint4*)(sBM + dst) = *(const uint4*)(wbM + src);
                    *(uint4*)(sBL + dst) = *(const uint4*)(wbL + src);
                }
                __syncthreads();
#pragma unroll
                for (int ks = 0; ks < 4; ks++) {
                    int ab = (w * 16 + g) * 72 + (ks << 4) + (tg << 1);
                    unsigned aH0 = *(const unsigned*)(sAH + ab);
                    unsigned aH1 = *(const unsigned*)(sAH + ab + 576);
                    unsigned aH2 = *(const unsigned*)(sAH + ab + 8);
                    unsigned aH3 = *(const unsigned*)(sAH + ab + 584);
                    unsigned aM0 = *(const unsigned*)(sAM + ab);
                    unsigned aM1 = *(const unsigned*)(sAM + ab + 576);
                    unsigned aM2 = *(const unsigned*)(sAM + ab + 8);
                    unsigned aM3 = *(const unsigned*)(sAM + ab + 584);
                    unsigned aL0 = *(const unsigned*)(sAL + ab);
                    unsigned aL1 = *(const unsigned*)(sAL + ab + 576);
                    unsigned aL2 = *(const unsigned*)(sAL + ab + 8);
                    unsigned aL3 = *(const unsigned*)(sAL + ab + 584);
#pragma unroll
                    for (int nt = 0; nt < 8; nt++) {
                        int bb = (nt * 8 + g) * 72 + (ks << 4) + (tg << 1);
                        unsigned bH0 = *(const unsigned*)(sBH + bb);
                        unsigned bH1 = *(const unsigned*)(sBH + bb + 8);
                        unsigned bM0 = *(const unsigned*)(sBM + bb);
                        unsigned bM1 = *(const unsigned*)(sBM + bb + 8);
                        unsigned bL0 = *(const unsigned*)(sBL + bb);
                        unsigned bL1 = *(const unsigned*)(sBL + bb + 8);
                        mma_bf16(la[nt], aH0, aH1, aH2, aH3, bH0, bH1);
                        mma_bf16(la[nt], aH0, aH1, aH2, aH3, bM0, bM1);
                        mma_bf16(la[nt], aM0, aM1, aM2, aM3, bH0, bH1);
                        mma_bf16(la[nt], aM0, aM1, aM2, aM3, bM0, bM1);
                        mma_bf16(la[nt], aH0, aH1, aH2, aH3, bL0, bL1);
                        mma_bf16(la[nt], aL0, aL1, aL2, aL3, bH0, bH1);
                    }
                }
                __syncthreads();
            }
            // argmax epilogue: lane holds rows r0=w*16+g, r1=r0+8; cols n0+nt*8+2tg(+1)
            int r0 = w * 16 + g, r1 = r0 + 8;
            unsigned long long b0 = 0ull, b1 = 0ull;
#pragma unroll
            for (int nt = 0; nt < 8; nt++) {
                int col = n0 + nt * 8 + (tg << 1);
                unsigned u;
                u = __float_as_uint(la[nt][0]);
                u = (u & 0x80000000u) ? ~u : (u | 0x80000000u);
                b0 = umax64(b0, ((unsigned long long)u << 32) | (unsigned)(VOC - 1 - col));
                u = __float_as_uint(la[nt][1]);
                u = (u & 0x80000000u) ? ~u : (u | 0x80000000u);
                b0 = umax64(b0, ((unsigned long long)u << 32) | (unsigned)(VOC - 2 - col));
                u = __float_as_uint(la[nt][2]);
                u = (u & 0x80000000u) ? ~u : (u | 0x80000000u);
                b1 = umax64(b1, ((unsigned long long)u << 32) | (unsigned)(VOC - 1 - col));
                u = __float_as_uint(la[nt][3]);
                u = (u & 0x80000000u) ? ~u : (u | 0x80000000u);
                b1 = umax64(b1, ((unsigned long long)u << 32) | (unsigned)(VOC - 2 - col));
            }
            b0 = umax64(b0, __shfl_xor_sync(0xffffffffu, b0, 1));
            b0 = umax64(b0, __shfl_xor_sync(0xffffffffu, b0, 2));
            b1 = umax64(b1, __shfl_xor_sync(0xffffffffu, b1, 1));
            b1 = umax64(b1, __shfl_xor_sync(0xffffffffu, b1, 2));
            if (tg == 0) {
                atomicMax(&g_amax[t * 128 + r0], b0);
                atomicMax(&g_amax[t * 128 + r1], b1);
            }
        }
        gsync();

        // ---- state machine (replicated per block; block 0 writes outputs) ----
        if (tid < 128) {
            int b = tid;
            unsigned long long key = g_amax[t * 128 + b];
            int col = (VOC - 1) - (int)(key & 0xffffffffu);
            int pos = s_pos[b], tip = s_tip[b], phr = s_phr[b], done = s_done[b];
            int live = !done;
            if (live && bx == 0) {
                out[b * MAXTOK + pos] = (float)col;
                out[OUT_GENM + b * MAXTOK + pos] = 1.0f;
            }
            pos += live;
            tip += live;
            int eos = (col == EOSTOK) && (tip >= 1);
            int sw = (eos || (tip >= MAXPER)) && live;
            phr += sw;
            if (sw) tip = 0;
            int cp = phr < 2 ? phr : 2;
            if (sw && phr < KPH && bx == 0) out[OUT_BOUNDS + b * 3 + cp] = (float)pos;
            done = done || (phr >= KPH) || (sw && !s_act[b * 3 + cp]);
            s_pos[b] = pos;
            s_tip[b] = tip;
            s_phr[b] = phr;
            s_done[b] = done;
            s_nxt[b] = col;
            s_gate[b] = (s_act[b * 3 + cp] && !done) ? 1.0f : 0.0f;
        }
        __syncthreads();
    }
}

// ---------------- host ----------------
extern "C" void kernel_launch(void* const* d_in, const int* in_sizes, int n_in,
                              void* d_out, int out_size)
{
    (void)in_sizes; (void)n_in; (void)out_size;
    const int dynBytes = 82944 + 64;
    cudaFuncSetAttribute(mega_kernel, cudaFuncAttributeMaxDynamicSharedMemorySize, dynBytes);
    mega_kernel<<<NBLK, NTHR, dynBytes>>>(
        (const float*)d_in[0],  (const float*)d_in[1],  (const float*)d_in[2],
        (const float*)d_in[3],  (const float*)d_in[4],  (const float*)d_in[5],
        (const float*)d_in[6],  (const float*)d_in[7],  (const float*)d_in[8],
        (const float*)d_in[9],  (const float*)d_in[10], (const float*)d_in[11],
        (const float*)d_in[12], (const float*)d_in[13], (const float*)d_in[14],
        (float*)d_out);
}

// round 11
// speedup vs baseline: 1.1317x; 1.0956x over previous
#include <cuda_runtime.h>
#include <cuda_bf16.h>
#include <cstdint>

// ---------------- constants ----------------
#define NBLK   296            /* 2 blocks per SM (148 SMs) */
#define NTHR   256
#define KPH    3
#define MAXPER 48
#define MAXTOK 144
#define CTOK   145
#define HD     512
#define VOC    8000
#define BOSTOK 1
#define EOSTOK 2

// ---------------- scratch offsets (floats) ----------------
#define O_WZ    0u
#define O_MEM   49152u
#define O_CK    1622016u
#define O_CV    3194880u
#define O_QP    4767744u
#define O_KP    5029888u
#define O_VP    5292032u
#define O_SAB   5554176u
#define O_P1    5619712u
#define O_X1    6668288u
#define O_CQP   6733824u
#define O_CAB   7782400u
#define O_P2    7847936u
#define O_X2    8896512u
#define O_W1P   8962048u
#define O_ACT   10010624u
#define O_W2P   10272768u
#define O_KC    11321344u
#define O_VC    20824064u
#define O_HIDB  30326784u   /* hid hi/mid/lo bf16: 3*65536 bf16 = 98304 floats */
#define O_WBF   30425088u   /* Wout hi/mid/lo bf16: 3*4096000 bf16 = 6144000 floats */
#define F_TOTAL 36569088u

// d_out: tokens[128*144] | genm[128*144] | bounds[128*3] | hiddens[144*128*512]
#define OUT_GENM   18432
#define OUT_BOUNDS 36864
#define OUT_HID    37248

__device__ static __align__(128) float g_f[F_TOTAL];
__device__ static unsigned long long g_amax[MAXTOK * 128];
__device__ static unsigned g_count;
__device__ static volatile unsigned g_gen;

// ---------------- helpers ----------------
__device__ __forceinline__ float gelu_tanh(float x) {
    float x3 = x * x * x;
    return 0.5f * x * (1.0f + tanhf(0.7978845608028654f * (x + 0.044715f * x3)));
}
__device__ __forceinline__ float wred(float p) {
    p += __shfl_xor_sync(0xffffffffu, p, 16);
    p += __shfl_xor_sync(0xffffffffu, p, 8);
    p += __shfl_xor_sync(0xffffffffu, p, 4);
    p += __shfl_xor_sync(0xffffffffu, p, 2);
    p += __shfl_xor_sync(0xffffffffu, p, 1);
    return p;
}
__device__ __forceinline__ unsigned long long umax64(unsigned long long a, unsigned long long b) {
    return a > b ? a : b;
}

__device__ __forceinline__ void gsync() {
    __syncthreads();
    if (threadIdx.x == 0) {
        unsigned gen = g_gen;
        __threadfence();
        if (atomicAdd(&g_count, 1u) == (unsigned)(NBLK - 1)) {
            g_count = 0u;
            __threadfence();
            g_gen = gen + 1u;
        } else {
            while (g_gen == gen) __nanosleep(64);
        }
        __threadfence();
    }
    __syncthreads();
}

// bf16 mma.sync m16n8k16 (base-target instruction; runs on tensor pipe as HMMA)
__device__ __forceinline__ void mma_bf16(float acc[4],
                                         unsigned a0, unsigned a1, unsigned a2, unsigned a3,
                                         unsigned b0, unsigned b1)
{
    asm volatile("mma.sync.aligned.m16n8k16.row.col.f32.bf16.bf16.f32 "
                 "{%0,%1,%2,%3}, {%4,%5,%6,%7}, {%8,%9}, {%0,%1,%2,%3};"
                 : "+f"(acc[0]), "+f"(acc[1]), "+f"(acc[2]), "+f"(acc[3])
                 : "r"(a0), "r"(a1), "r"(a2), "r"(a3), "r"(b0), "r"(b1));
}

// ---------------- 128x64 FFMA tile core (non-logits GEMMs) ----------------
__device__ __forceinline__ void run_tile64(
    const float* __restrict__ A, const int* gidx, int lda,
    const float* __restrict__ W, int ldw, int wcol,
    int kOff, int kChunk, float* sA, float* sW, float acc[4][8])
{
    const int tid  = threadIdx.x;
    const int arow = tid >> 3, ak4 = (tid & 7) << 2;
    const int wn8  = (tid & 7) << 3;
    const int rg4  = (tid >> 3) << 2, cg8 = (tid & 7) << 3;

    const float* Arow[4];
#pragma unroll
    for (int i = 0; i < 4; i++) {
        int r = arow + (i << 5);
        int rr = gidx ? gidx[r] : r;
        Arow[i] = A + (size_t)rr * lda + kOff + ak4;
    }
    const float* Wp = W + (size_t)(kOff + arow) * ldw + wcol + wn8;

#pragma unroll
    for (int i = 0; i < 4; i++)
#pragma unroll
        for (int j = 0; j < 8; j++) acc[i][j] = 0.f;

    float4 pa0 = *(const float4*)(Arow[0]);
    float4 pa1 = *(const float4*)(Arow[1]);
    float4 pa2 = *(const float4*)(Arow[2]);
    float4 pa3 = *(const float4*)(Arow[3]);
    float4 pw0 = *(const float4*)(Wp);
    float4 pw1 = *(const float4*)(Wp + 4);

    for (int kt = 0; kt < kChunk; kt += 32) {
        sA[(ak4 + 0) * 132 + arow      ] = pa0.x;
        sA[(ak4 + 1) * 132 + arow      ] = pa0.y;
        sA[(ak4 + 2) * 132 + arow      ] = pa0.z;
        sA[(ak4 + 3) * 132 + arow      ] = pa0.w;
        sA[(ak4 + 0) * 132 + arow + 32 ] = pa1.x;
        sA[(ak4 + 1) * 132 + arow + 32 ] = pa1.y;
        sA[(ak4 + 2) * 132 + arow + 32 ] = pa1.z;
        sA[(ak4 + 3) * 132 + arow + 32 ] = pa1.w;
        sA[(ak4 + 0) * 132 + arow + 64 ] = pa2.x;
        sA[(ak4 + 1) * 132 + arow + 64 ] = pa2.y;
        sA[(ak4 + 2) * 132 + arow + 64 ] = pa2.z;
        sA[(ak4 + 3) * 132 + arow + 64 ] = pa2.w;
        sA[(ak4 + 0) * 132 + arow + 96 ] = pa3.x;
        sA[(ak4 + 1) * 132 + arow + 96 ] = pa3.y;
        sA[(ak4 + 2) * 132 + arow + 96 ] = pa3.z;
        sA[(ak4 + 3) * 132 + arow + 96 ] = pa3.w;
        *(float4*)&sW[arow * 64 + wn8    ] = pw0;
        *(float4*)&sW[arow * 64 + wn8 + 4] = pw1;
        __syncthreads();

        if (kt + 32 < kChunk) {
            pa0 = *(const float4*)(Arow[0] + kt + 32);
            pa1 = *(const float4*)(Arow[1] + kt + 32);
            pa2 = *(const float4*)(Arow[2] + kt + 32);
            pa3 = *(const float4*)(Arow[3] + kt + 32);
            pw0 = *(const float4*)(Wp + (size_t)(kt + 32) * ldw);
            pw1 = *(const float4*)(Wp + (size_t)(kt + 32) * ldw + 4);
        }

#pragma unroll
        for (int kk = 0; kk < 32; kk++) {
            float4 av  = *(const float4*)&sA[kk * 132 + rg4];
            float4 w0v = *(const float4*)&sW[kk * 64 + cg8];
            float4 w1v = *(const float4*)&sW[kk * 64 + cg8 + 4];
            acc[0][0] += av.x * w0v.x; acc[0][1] += av.x * w0v.y; acc[0][2] += av.x * w0v.z; acc[0][3] += av.x * w0v.w;
            acc[0][4] += av.x * w1v.x; acc[0][5] += av.x * w1v.y; acc[0][6] += av.x * w1v.z; acc[0][7] += av.x * w1v.w;
            acc[1][0] += av.y * w0v.x; acc[1][1] += av.y * w0v.y; acc[1][2] += av.y * w0v.z; acc[1][3] += av.y * w0v.w;
            acc[1][4] += av.y * w1v.x; acc[1][5] += av.y * w1v.y; acc[1][6] += av.y * w1v.z; acc[1][7] += av.y * w1v.w;
            acc[2][0] += av.z * w0v.x; acc[2][1] += av.z * w0v.y; acc[2][2] += av.z * w0v.z; acc[2][3] += av.z * w0v.w;
            acc[2][4] += av.z * w1v.x; acc[2][5] += av.z * w1v.y; acc[2][6] += av.z * w1v.z; acc[2][7] += av.z * w1v.w;
            acc[3][0] += av.w * w0v.x; acc[3][1] += av.w * w0v.y; acc[3][2] += av.w * w0v.z; acc[3][3] += av.w * w0v.w;
            acc[3][4] += av.w * w1v.x; acc[3][5] += av.w * w1v.y; acc[3][6] += av.w * w1v.z; acc[3][7] += av.w * w1v.w;
        }
        __syncthreads();
    }
}

__device__ __forceinline__ void store_tile64(float* __restrict__ C, int ldc, int colBase,
                                             const float acc[4][8])
{
    const int rg4 = (threadIdx.x >> 3) << 2, cg8 = (threadIdx.x & 7) << 3;
#pragma unroll
    for (int i = 0; i < 4; i++) {
        float* p = C + (size_t)(rg4 + i) * ldc + colBase + cg8;
        *(float4*)p       = make_float4(acc[i][0], acc[i][1], acc[i][2], acc[i][3]);
        *(float4*)(p + 4) = make_float4(acc[i][4], acc[i][5], acc[i][6], acc[i][7]);
    }
}

__device__ __forceinline__ float sum16(const float* p, int i) {
    float a = (p[i] + p[65536 + i]) + (p[131072 + i] + p[196608 + i]);
    float b = (p[262144 + i] + p[327680 + i]) + (p[393216 + i] + p[458752 + i]);
    float c = (p[524288 + i] + p[589824 + i]) + (p[655360 + i] + p[720896 + i]);
    float d = (p[786432 + i] + p[851968 + i]) + (p[917504 + i] + p[983040 + i]);
    return (a + b) + (c + d);
}

// ---------------- persistent mega-kernel ----------------
__global__ void __launch_bounds__(NTHR, 2) mega_kernel(
    const float* __restrict__ z_seq, const float* __restrict__ z_w,
    const float* __restrict__ Wl2d, const float* __restrict__ temb,
    const float* __restrict__ Wq,  const float* __restrict__ Wk,
    const float* __restrict__ Wv,  const float* __restrict__ Wo,
    const float* __restrict__ Wcq, const float* __restrict__ Wck,
    const float* __restrict__ Wcv, const float* __restrict__ Wco,
    const float* __restrict__ W1,  const float* __restrict__ W2,
    const float* __restrict__ Wout, float* __restrict__ out)
{
    __shared__ float s_q[8 * 64];
    __shared__ float s_sc[8 * 152];
    __shared__ int   s_act[384];
    __shared__ int   s_pos[128], s_tip[128], s_phr[128], s_done[128], s_nxt[128];
    __shared__ float s_gate[128];
    extern __shared__ __align__(16) char dsm[];

    // dynamic smem UNION:
    //  FFMA view: sA float[32*132] (16896 B) + sW float[32*64] (8192 B) = 25088 B
    //  MMA  view: A splits 3*(128*72*2=18432 B) + B splits 3*(32*72*2=4608 B) = 69120 B
    float* sA = (float*)dsm;
    float* sW = (float*)(dsm + 16896);
    __nv_bfloat16* sAH = (__nv_bfloat16*)dsm;
    __nv_bfloat16* sAM = sAH + 9216;
    __nv_bfloat16* sAL = sAM + 9216;
    __nv_bfloat16* sBH = sAL + 9216;
    __nv_bfloat16* sBM = sBH + 2304;
    __nv_bfloat16* sBL = sBM + 2304;

    const int tid = threadIdx.x;
    const int bx  = blockIdx.x;
    const int gid = bx * NTHR + tid;
    const int gsz = NBLK * NTHR;   // 75776
    float acc[4][8];

    float* wz  = g_f + O_WZ;
    float* mem = g_f + O_MEM;
    float* ckb = g_f + O_CK;
    float* cvb = g_f + O_CV;
    float* qp  = g_f + O_QP;
    float* kp  = g_f + O_KP;
    float* vp  = g_f + O_VP;
    float* sab = g_f + O_SAB;
    float* p1  = g_f + O_P1;
    float* x1  = g_f + O_X1;
    float* cqp = g_f + O_CQP;
    float* cab = g_f + O_CAB;
    float* p2  = g_f + O_P2;
    float* x2  = g_f + O_X2;
    float* w1p = g_f + O_W1P;
    float* act = g_f + O_ACT;
    float* w2p = g_f + O_W2P;
    float* kc  = g_f + O_KC;
    float* vc  = g_f + O_VC;
    __nv_bfloat16* hidH = (__nv_bfloat16*)(g_f + O_HIDB);
    __nv_bfloat16* hidM = hidH + 65536;
    __nv_bfloat16* hidL = hidM + 65536;
    __nv_bfloat16* wbH  = (__nv_bfloat16*)(g_f + O_WBF);
    __nv_bfloat16* wbM  = wbH + 4096000;
    __nv_bfloat16* wbL  = wbM + 4096000;

    // ---- init ----
    for (int i = gid; i < 49152; i += gsz) wz[i] = z_w[i >> 7] * z_seq[i];
    for (int i = gid; i < OUT_HID; i += gsz) out[i] = 0.f;
    for (int i = gid; i < MAXTOK * 128; i += gsz) g_amax[i] = 0ull;
    // split Wout[k,8000] into bf16 hi/mid/lo, laid out [n][k] (K-major rows = col-major B)
    for (int i = gid; i < 4096000; i += gsz) {
        int n = i >> 9, k = i & 511;
        float v = Wout[(size_t)k * VOC + n];
        __nv_bfloat16 h = __float2bfloat16(v);
        float r = v - __bfloat162float(h);
        __nv_bfloat16 m = __float2bfloat16(r);
        float r2 = r - __bfloat162float(m);
        wbH[i] = h; wbM[i] = m; wbL[i] = __float2bfloat16(r2);
    }
    for (int i = tid; i < 384; i += NTHR) s_act[i] = (z_w[i] > 0.01f) ? 1 : 0;
    if (tid < 128) {
        s_pos[tid] = 0; s_tip[tid] = 0; s_phr[tid] = 0;
        int a0 = (z_w[tid * 3] > 0.01f) ? 1 : 0;
        s_done[tid] = !a0;
        s_nxt[tid]  = BOSTOK;
        s_gate[tid] = a0 ? 1.f : 0.f;
    }
    gsync();

    // ---- memories = wz[384,128] @ Wl2d[128,4096] : 192 tiles ----
    for (int tile = bx; tile < 192; tile += NBLK) {
        int by = tile >> 6, cx = tile & 63;
        run_tile64(wz + (size_t)by * 128 * 128, nullptr, 128, Wl2d, 4096, cx * 64,
                   0, 128, sA, sW, acc);
        store_tile64(mem + (size_t)by * 128 * 4096, 4096, cx * 64, acc);
    }
    gsync();

    // ---- ck/cv = mem[3072,512] @ Wck/Wcv : 384 tiles ----
    for (int tile = bx; tile < 384; tile += NBLK) {
        int isv = tile >= 192;
        int idx = isv ? tile - 192 : tile;
        int by = idx >> 3, cx = idx & 7;
        run_tile64(mem + (size_t)by * 65536, nullptr, 512, isv ? Wcv : Wck, 512, cx * 64,
                   0, 512, sA, sW, acc);
        store_tile64((isv ? cvb : ckb) + (size_t)by * 65536, 512, cx * 64, acc);
    }
    gsync();

    // ================= decode loop =================
    for (int t = 0; t < MAXTOK; t++) {
        // ---- QKV: splitK4 (chunk 128), 96 tiles ----
        for (int tile = bx; tile < 96; tile += NBLK) {
            int sel = tile >> 5, rem = tile & 31;
            int ks = rem >> 3, cx = rem & 7;
            const float* W_ = (sel == 0) ? Wq : ((sel == 1) ? Wk : Wv);
            float* C_ = (sel == 0) ? qp : ((sel == 1) ? kp : vp);
            run_tile64(temb, s_nxt, 512, W_, 512, cx * 64, ks * 128, 128, sA, sW, acc);
            store_tile64(C_ + ks * 65536, 512, cx * 64, acc);
        }
        gsync();

        // ---- attention (first 128 blocks, 8 warps each = 1024 warps) ----
        {
            int wid = tid >> 5, lane = tid & 31;
            int gw = bx * 8 + wid;
            if (gw < 1024) {
                int b = gw >> 3, h = gw & 7;
                int off = b * 512 + h * 64 + lane * 2;
                float2 qv = make_float2(0.f, 0.f), kv2 = qv, vv2 = qv;
#pragma unroll
                for (int j = 0; j < 4; j++) {
                    float2 a = *(const float2*)(qp + j * 65536 + off);
                    float2 c = *(const float2*)(kp + j * 65536 + off);
                    float2 d = *(const float2*)(vp + j * 65536 + off);
                    qv.x += a.x; qv.y += a.y;
                    kv2.x += c.x; kv2.y += c.y;
                    vv2.x += d.x; vv2.y += d.y;
                }
                float* krow = kc + (size_t)(b * 8 + h) * CTOK * 64;
                float* vrow = vc + (size_t)(b * 8 + h) * CTOK * 64;
                *(float2*)(krow + (size_t)t * 64 + lane * 2) = kv2;
                *(float2*)(vrow + (size_t)t * 64 + lane * 2) = vv2;
                float* sqw = s_q + wid * 64;
                float* scw = s_sc + wid * 152;
                *(float2*)(sqw + lane * 2) = qv;
                __syncwarp();
                for (int s = lane; s < t; s += 32) {
                    const float* kr = krow + (size_t)s * 64;
                    float d = 0.f;
#pragma unroll
                    for (int c = 0; c < 16; c++) {
                        float4 kv = *(const float4*)(kr + c * 4);
                        float4 qq = *(const float4*)(sqw + c * 4);
                        d += kv.x * qq.x + kv.y * qq.y + kv.z * qq.z + kv.w * qq.w;
                    }
                    scw[s] = d * 0.125f;
                }
                float pt = wred(qv.x * kv2.x + qv.y * kv2.y) * 0.125f;
                if (lane == 0) scw[t] = pt;
                __syncwarp();
                int n = t + 1;
                float mx = -1e30f;
                for (int s = lane; s < n; s += 32) mx = fmaxf(mx, scw[s]);
                for (int o = 16; o; o >>= 1) mx = fmaxf(mx, __shfl_xor_sync(0xffffffffu, mx, o));
                float sum = 0.f;
                for (int s = lane; s < n; s += 32) {
                    float e = expf(scw[s] - mx);
                    scw[s] = e;
                    sum += e;
                }
                for (int o = 16; o; o >>= 1) sum += __shfl_xor_sync(0xffffffffu, sum, o);
                float inv = 1.0f / sum;
                __syncwarp();
                float a0 = 0.f, a1 = 0.f;
                for (int s = 0; s < t; s++) {
                    float p = scw[s] * inv;
                    float2 vv = *(const float2*)(vrow + (size_t)s * 64 + lane * 2);
                    a0 += p * vv.x;
                    a1 += p * vv.y;
                }
                float ptn = scw[t] * inv;
                a0 += ptn * vv2.x;
                a1 += ptn * vv2.y;
                *(float2*)(sab + off) = make_float2(a0, a1);
            }
        }
        gsync();

        // ---- Wo: splitK16 (chunk 32), 128 tiles ----
        for (int tile = bx; tile < 128; tile += NBLK) {
            int cx = tile & 7, ks = tile >> 3;
            run_tile64(sab, nullptr, 512, Wo, 512, cx * 64, ks * 32, 32, sA, sW, acc);
            store_tile64(p1 + ks * 65536, 512, cx * 64, acc);
        }
        gsync();

        // ---- x1 = temb[nxt] + sum16(p1) ----
        for (int i = gid; i < 65536; i += gsz)
            x1[i] = temb[(size_t)s_nxt[i >> 9] * 512 + (i & 511)] + sum16(p1, i);
        gsync();

        // ---- cq: splitK16, 128 tiles ----
        for (int tile = bx; tile < 128; tile += NBLK) {
            int cx = tile & 7, ks = tile >> 3;
            run_tile64(x1, nullptr, 512, Wcq, 512, cx * 64, ks * 32, 32, sA, sW, acc);
            store_tile64(cqp + ks * 65536, 512, cx * 64, acc);
        }
        gsync();

        // ---- cross-attention ----
        {
            int wid = tid >> 5, lane = tid & 31;
            int gw = bx * 8 + wid;
            if (gw < 1024) {
                int b = gw >> 3, h = gw & 7;
                int off = b * 512 + h * 64 + lane * 2;
                float qx = 0.f, qy = 0.f;
#pragma unroll
                for (int j = 0; j < 16; j++) {
                    float2 p = *(const float2*)(cqp + j * 65536 + off);
                    qx += p.x; qy += p.y;
                }
                int phr = s_phr[b];
                int i = phr < 2 ? phr : 2;
                float g = s_gate[b];
                size_t base = (size_t)((b * 3 + i) * 8) * 512 + h * 64 + lane * 2;
                const float* Kp = ckb + base;
                const float* Vp = cvb + base;
                float s[8], mx = -1e30f;
#pragma unroll
                for (int m = 0; m < 8; m++) {
                    float2 kv = *(const float2*)(Kp + m * 512);
                    s[m] = wred(qx * kv.x + qy * kv.y) * 0.125f;
                    mx = fmaxf(mx, s[m]);
                }
                float sum = 0.f;
#pragma unroll
                for (int m = 0; m < 8; m++) { s[m] = expf(s[m] - mx); sum += s[m]; }
                float inv = 1.0f / sum;
                float a0 = 0.f, a1 = 0.f;
#pragma unroll
                for (int m = 0; m < 8; m++) {
                    float2 vv = *(const float2*)(Vp + m * 512);
                    a0 += s[m] * vv.x;
                    a1 += s[m] * vv.y;
                }
                *(float2*)(cab + off) = make_float2(a0 * inv * g, a1 * inv * g);
            }
        }
        gsync();

        // ---- Wco: splitK16, 128 tiles ----
        for (int tile = bx; tile < 128; tile += NBLK) {
            int cx = tile & 7, ks = tile >> 3;
            run_tile64(cab, nullptr, 512, Wco, 512, cx * 64, ks * 32, 32, sA, sW, acc);
            store_tile64(p2 + ks * 65536, 512, cx * 64, acc);
        }
        gsync();

        // ---- x2 = x1 + sum16(p2) ----
        for (int i = gid; i < 65536; i += gsz)
            x2[i] = x1[i] + sum16(p2, i);
        gsync();

        // ---- W1: splitK4 (chunk 128), 128 tiles ----
        for (int tile = bx; tile < 128; tile += NBLK) {
            int cx = tile & 31, ks = tile >> 5;
            run_tile64(x2, nullptr, 512, W1, 2048, cx * 64, ks * 128, 128, sA, sW, acc);
            store_tile64(w1p + ks * 262144, 2048, cx * 64, acc);
        }
        gsync();

        // ---- act = gelu(sum4(w1p)) ----
        for (int i = gid; i < 262144; i += gsz)
            act[i] = gelu_tanh((w1p[i] + w1p[262144 + i]) + (w1p[524288 + i] + w1p[786432 + i]));
        gsync();

        // ---- W2: splitK16 (chunk 128), 128 tiles ----
        for (int tile = bx; tile < 128; tile += NBLK) {
            int cx = tile & 7, ks = tile >> 3;
            run_tile64(act, nullptr, 2048, W2, 512, cx * 64, ks * 128, 128, sA, sW, acc);
            store_tile64(w2p + ks * 65536, 512, cx * 64, acc);
        }
        gsync();

        // ---- hid = x2 + sum16(w2p) -> out, fused hi/mid/lo bf16 split ----
        float* hid = out + OUT_HID + (size_t)t * 65536;
        for (int i = gid; i < 65536; i += gsz) {
            float v = x2[i] + sum16(w2p, i);
            hid[i] = v;
            __nv_bfloat16 h = __float2bfloat16(v);
            float r = v - __bfloat162float(h);
            __nv_bfloat16 m = __float2bfloat16(r);
            hidH[i] = h; hidM[i] = m;
            hidL[i] = __float2bfloat16(r - __bfloat162float(m));
        }
        gsync();

        // ---- logits via mma.sync bf16x6 emulated fp32 + fused argmax ----
        // 250 blocks, 32-col vocab slabs each
        if (bx < 250) {
            const int n0 = bx * 32;
            const int w = tid >> 5, lane = tid & 31;
            const int g = lane >> 2, tg = lane & 3;
            float la[4][4];
#pragma unroll
            for (int nt = 0; nt < 4; nt++)
#pragma unroll
                for (int j = 0; j < 4; j++) la[nt][j] = 0.f;

            for (int kchunk = 0; kchunk < 8; kchunk++) {
                // stage A chunk [128 x 64] x3 splits (pitch 72)
                for (int i = tid; i < 1024; i += NTHR) {
                    int row = i >> 3, c8 = (i & 7) << 3;
                    size_t src = (size_t)row * 512 + (kchunk << 6) + c8;
                    int dst = row * 72 + c8;
                    *(uint4*)(sAH + dst) = *(const uint4*)(hidH + src);
                    *(uint4*)(sAM + dst) = *(const uint4*)(hidM + src);
                    *(uint4*)(sAL + dst) = *(const uint4*)(hidL + src);
                }
                // stage B chunk [32n x 64k] x3 splits (pitch 72)
                for (int i = tid; i < 256; i += NTHR) {
                    int row = i >> 3, c8 = (i & 7) << 3;
                    size_t src = (size_t)(n0 + row) * 512 + (kchunk << 6) + c8;
                    int dst = row * 72 + c8;
                    *(uint4*)(sBH + dst) = *(const uint4*)(wbH + src);
                    *(uint4*)(sBM + dst) = *(const uint4*)(wbM + src);
                    *(uint4*)(sBL + dst) = *(const uint4*)(wbL + src);
                }
                __syncthreads();
#pragma unroll
                for (int ks = 0; ks < 4; ks++) {
                    int ab = (w * 16 + g) * 72 + (ks << 4) + (tg << 1);
                    unsigned aH0 = *(const unsigned*)(sAH + ab);
                    unsigned aH1 = *(const unsigned*)(sAH + ab + 576);
                    unsigned aH2 = *(const unsigned*)(sAH + ab + 8);
                    unsigned aH3 = *(const unsigned*)(sAH + ab + 584);
                    unsigned aM0 = *(const unsigned*)(sAM + ab);
                    unsigned aM1 = *(const unsigned*)(sAM + ab + 576);
                    unsigned aM2 = *(const unsigned*)(sAM + ab + 8);
                    unsigned aM3 = *(const unsigned*)(sAM + ab + 584);
                    unsigned aL0 = *(const unsigned*)(sAL + ab);
                    unsigned aL1 = *(const unsigned*)(sAL + ab + 576);
                    unsigned aL2 = *(const unsigned*)(sAL + ab + 8);
                    unsigned aL3 = *(const unsigned*)(sAL + ab + 584);
#pragma unroll
                    for (int nt = 0; nt < 4; nt++) {
                        int bb = (nt * 8 + g) * 72 + (ks << 4) + (tg << 1);
                        unsigned bH0 = *(const unsigned*)(sBH + bb);
                        unsigned bH1 = *(const unsigned*)(sBH + bb + 8);
                        unsigned bM0 = *(const unsigned*)(sBM + bb);
                        unsigned bM1 = *(const unsigned*)(sBM + bb + 8);
                        unsigned bL0 = *(const unsigned*)(sBL + bb);
                        unsigned bL1 = *(const unsigned*)(sBL + bb + 8);
                        mma_bf16(la[nt], aH0, aH1, aH2, aH3, bH0, bH1);
                        mma_bf16(la[nt], aH0, aH1, aH2, aH3, bM0, bM1);
                        mma_bf16(la[nt], aM0, aM1, aM2, aM3, bH0, bH1);
                        mma_bf16(la[nt], aM0, aM1, aM2, aM3, bM0, bM1);
                        mma_bf16(la[nt], aH0, aH1, aH2, aH3, bL0, bL1);
                        mma_bf16(la[nt], aL0, aL1, aL2, aL3, bH0, bH1);
                    }
                }
                __syncthreads();
            }
            // argmax epilogue: lane holds rows r0=w*16+g, r1=r0+8; cols n0+nt*8+2tg(+1)
            int r0 = w * 16 + g, r1 = r0 + 8;
            unsigned long long b0 = 0ull, b1 = 0ull;
#pragma unroll
            for (int nt = 0; nt < 4; nt++) {
                int col = n0 + nt * 8 + (tg << 1);
                unsigned u;
                u = __float_as_uint(la[nt][0]);
                u = (u & 0x80000000u) ? ~u : (u | 0x80000000u);
                b0 = umax64(b0, ((unsigned long long)u << 32) | (unsigned)(VOC - 1 - col));
                u = __float_as_uint(la[nt][1]);
                u = (u & 0x80000000u) ? ~u : (u | 0x80000000u);
                b0 = umax64(b0, ((unsigned long long)u << 32) | (unsigned)(VOC - 2 - col));
                u = __float_as_uint(la[nt][2]);
                u = (u & 0x80000000u) ? ~u : (u | 0x80000000u);
                b1 = umax64(b1, ((unsigned long long)u << 32) | (unsigned)(VOC - 1 - col));
                u = __float_as_uint(la[nt][3]);
                u = (u & 0x80000000u) ? ~u : (u | 0x80000000u);
                b1 = umax64(b1, ((unsigned long long)u << 32) | (unsigned)(VOC - 2 - col));
            }
            b0 = umax64(b0, __shfl_xor_sync(0xffffffffu, b0, 1));
            b0 = umax64(b0, __shfl_xor_sync(0xffffffffu, b0, 2));
            b1 = umax64(b1, __shfl_xor_sync(0xffffffffu, b1, 1));
            b1 = umax64(b1, __shfl_xor_sync(0xffffffffu, b1, 2));
            if (tg == 0) {
                atomicMax(&g_amax[t * 128 + r0], b0);
                atomicMax(&g_amax[t * 128 + r1], b1);
            }
        }
        gsync();

        // ---- state machine (replicated per block; block 0 writes outputs) ----
        if (tid < 128) {
            int b = tid;
            unsigned long long key = g_amax[t * 128 + b];
            int col = (VOC - 1) - (int)(key & 0xffffffffu);
            int pos = s_pos[b], tip = s_tip[b], phr = s_phr[b], done = s_done[b];
            int live = !done;
            if (live && bx == 0) {
                out[b * MAXTOK + pos] = (float)col;
                out[OUT_GENM + b * MAXTOK + pos] = 1.0f;
            }
            pos += live;
            tip += live;
            int eos = (col == EOSTOK) && (tip >= 1);
            int sw = (eos || (tip >= MAXPER)) && live;
            phr += sw;
            if (sw) tip = 0;
            int cp = phr < 2 ? phr : 2;
            if (sw && phr < KPH && bx == 0) out[OUT_BOUNDS + b * 3 + cp] = (float)pos;
            done = done || (phr >= KPH) || (sw && !s_act[b * 3 + cp]);
            s_pos[b] = pos;
            s_tip[b] = tip;
            s_phr[b] = phr;
            s_done[b] = done;
            s_nxt[b] = col;
            s_gate[b] = (s_act[b * 3 + cp] && !done) ? 1.0f : 0.0f;
        }
        __syncthreads();
    }
}

// ---------------- host ----------------
extern "C" void kernel_launch(void* const* d_in, const int* in_sizes, int n_in,
                              void* d_out, int out_size)
{
    (void)in_sizes; (void)n_in; (void)out_size;
    const int dynBytes = 69120;
    cudaFuncSetAttribute(mega_kernel, cudaFuncAttributeMaxDynamicSharedMemorySize, dynBytes);
    mega_kernel<<<NBLK, NTHR, dynBytes>>>(
        (const float*)d_in[0],  (const float*)d_in[1],  (const float*)d_in[2],
        (const float*)d_in[3],  (const float*)d_in[4],  (const float*)d_in[5],
        (const float*)d_in[6],  (const float*)d_in[7],  (const float*)d_in[8],
        (const float*)d_in[9],  (const float*)d_in[10], (const float*)d_in[11],
        (const float*)d_in[12], (const float*)d_in[13], (const float*)d_in[14],
        (float*)d_out);
}

// round 12
// speedup vs baseline: 1.1960x; 1.0568x over previous
#include <cuda_runtime.h>
#include <cuda_bf16.h>
#include <cstdint>

// ---------------- constants ----------------
#define NBLK   296            /* 2 blocks per SM (148 SMs) */
#define NTHR   256
#define KPH    3
#define MAXPER 48
#define MAXTOK 144
#define CTOK   145
#define HD     512
#define VOC    8000
#define BOSTOK 1
#define EOSTOK 2

// ---------------- scratch offsets (floats) ----------------
#define O_WZ     0u
#define O_MEM    49152u
#define O_CK     1622016u
#define O_CV     3194880u
#define O_QP     4767744u      /* 8 x 65536 */
#define O_KP     5292032u      /* 8 x 65536 */
#define O_VP     5816320u      /* 8 x 65536 */
#define O_SAB    6340608u
#define O_P1     6406144u      /* 8 x 65536 */
#define O_CQA    6930432u      /* 8 x 65536 */
#define O_CQB    7454720u      /* 8 x 65536 */
#define O_X1     7979008u
#define O_CAB    8044544u
#define O_P2     8110080u      /* 4 x 65536 */
#define O_W1A    8372224u      /* 4 x 262144 */
#define O_W1B    9420800u      /* 4 x 262144 */
#define O_ACT    10469376u     /* 262144 */
#define O_X2     10731520u
#define O_W2P    10797056u     /* 16 x 65536 */
#define O_WOCQ   11845632u     /* Wo@Wcq 512x512 */
#define O_WCOW1  12107776u     /* Wco@W1 512x2048 */
#define O_KC     13156352u
#define O_VC     22659072u
#define O_HIDB   32161792u     /* hid hi/mid/lo bf16 */
#define O_WBF    32260096u     /* Wout hi/mid/lo bf16 */
#define F_TOTAL  38404096u

// d_out: tokens[128*144] | genm[128*144] | bounds[128*3] | hiddens[144*128*512]
#define OUT_GENM   18432
#define OUT_BOUNDS 36864
#define OUT_HID    37248

__device__ static __align__(128) float g_f[F_TOTAL];
__device__ static unsigned long long g_amax[MAXTOK * 128];
__device__ static unsigned g_count;
__device__ static volatile unsigned g_gen;

// ---------------- helpers ----------------
__device__ __forceinline__ float gelu_tanh(float x) {
    float x3 = x * x * x;
    return 0.5f * x * (1.0f + tanhf(0.7978845608028654f * (x + 0.044715f * x3)));
}
__device__ __forceinline__ float wred(float p) {
    p += __shfl_xor_sync(0xffffffffu, p, 16);
    p += __shfl_xor_sync(0xffffffffu, p, 8);
    p += __shfl_xor_sync(0xffffffffu, p, 4);
    p += __shfl_xor_sync(0xffffffffu, p, 2);
    p += __shfl_xor_sync(0xffffffffu, p, 1);
    return p;
}
__device__ __forceinline__ unsigned long long umax64(unsigned long long a, unsigned long long b) {
    return a > b ? a : b;
}

__device__ __forceinline__ void gsync() {
    __syncthreads();
    if (threadIdx.x == 0) {
        unsigned gen = g_gen;
        __threadfence();
        if (atomicAdd(&g_count, 1u) == (unsigned)(NBLK - 1)) {
            g_count = 0u;
            __threadfence();
            g_gen = gen + 1u;
        } else {
            while (g_gen == gen) __nanosleep(64);
        }
        __threadfence();
    }
    __syncthreads();
}

// bf16 mma.sync m16n8k16 (base-target instruction; runs on tensor pipe as HMMA)
__device__ __forceinline__ void mma_bf16(float acc[4],
                                         unsigned a0, unsigned a1, unsigned a2, unsigned a3,
                                         unsigned b0, unsigned b1)
{
    asm volatile("mma.sync.aligned.m16n8k16.row.col.f32.bf16.bf16.f32 "
                 "{%0,%1,%2,%3}, {%4,%5,%6,%7}, {%8,%9}, {%0,%1,%2,%3};"
                 : "+f"(acc[0]), "+f"(acc[1]), "+f"(acc[2]), "+f"(acc[3])
                 : "r"(a0), "r"(a1), "r"(a2), "r"(a3), "r"(b0), "r"(b1));
}

// ---------------- 128x64 FFMA tile core ----------------
__device__ __forceinline__ void run_tile64(
    const float* __restrict__ A, const int* gidx, int lda,
    const float* __restrict__ W, int ldw, int wcol,
    int kOff, int kChunk, float* sA, float* sW, float acc[4][8])
{
    const int tid  = threadIdx.x;
    const int arow = tid >> 3, ak4 = (tid & 7) << 2;
    const int wn8  = (tid & 7) << 3;
    const int rg4  = (tid >> 3) << 2, cg8 = (tid & 7) << 3;

    const float* Arow[4];
#pragma unroll
    for (int i = 0; i < 4; i++) {
        int r = arow + (i << 5);
        int rr = gidx ? gidx[r] : r;
        Arow[i] = A + (size_t)rr * lda + kOff + ak4;
    }
    const float* Wp = W + (size_t)(kOff + arow) * ldw + wcol + wn8;

#pragma unroll
    for (int i = 0; i < 4; i++)
#pragma unroll
        for (int j = 0; j < 8; j++) acc[i][j] = 0.f;

    float4 pa0 = *(const float4*)(Arow[0]);
    float4 pa1 = *(const float4*)(Arow[1]);
    float4 pa2 = *(const float4*)(Arow[2]);
    float4 pa3 = *(const float4*)(Arow[3]);
    float4 pw0 = *(const float4*)(Wp);
    float4 pw1 = *(const float4*)(Wp + 4);

    for (int kt = 0; kt < kChunk; kt += 32) {
        sA[(ak4 + 0) * 132 + arow      ] = pa0.x;
        sA[(ak4 + 1) * 132 + arow      ] = pa0.y;
        sA[(ak4 + 2) * 132 + arow      ] = pa0.z;
        sA[(ak4 + 3) * 132 + arow      ] = pa0.w;
        sA[(ak4 + 0) * 132 + arow + 32 ] = pa1.x;
        sA[(ak4 + 1) * 132 + arow + 32 ] = pa1.y;
        sA[(ak4 + 2) * 132 + arow + 32 ] = pa1.z;
        sA[(ak4 + 3) * 132 + arow + 32 ] = pa1.w;
        sA[(ak4 + 0) * 132 + arow + 64 ] = pa2.x;
        sA[(ak4 + 1) * 132 + arow + 64 ] = pa2.y;
        sA[(ak4 + 2) * 132 + arow + 64 ] = pa2.z;
        sA[(ak4 + 3) * 132 + arow + 64 ] = pa2.w;
        sA[(ak4 + 0) * 132 + arow + 96 ] = pa3.x;
        sA[(ak4 + 1) * 132 + arow + 96 ] = pa3.y;
        sA[(ak4 + 2) * 132 + arow + 96 ] = pa3.z;
        sA[(ak4 + 3) * 132 + arow + 96 ] = pa3.w;
        *(float4*)&sW[arow * 64 + wn8    ] = pw0;
        *(float4*)&sW[arow * 64 + wn8 + 4] = pw1;
        __syncthreads();

        if (kt + 32 < kChunk) {
            pa0 = *(const float4*)(Arow[0] + kt + 32);
            pa1 = *(const float4*)(Arow[1] + kt + 32);
            pa2 = *(const float4*)(Arow[2] + kt + 32);
            pa3 = *(const float4*)(Arow[3] + kt + 32);
            pw0 = *(const float4*)(Wp + (size_t)(kt + 32) * ldw);
            pw1 = *(const float4*)(Wp + (size_t)(kt + 32) * ldw + 4);
        }

#pragma unroll
        for (int kk = 0; kk < 32; kk++) {
            float4 av  = *(const float4*)&sA[kk * 132 + rg4];
            float4 w0v = *(const float4*)&sW[kk * 64 + cg8];
            float4 w1v = *(const float4*)&sW[kk * 64 + cg8 + 4];
            acc[0][0] += av.x * w0v.x; acc[0][1] += av.x * w0v.y; acc[0][2] += av.x * w0v.z; acc[0][3] += av.x * w0v.w;
            acc[0][4] += av.x * w1v.x; acc[0][5] += av.x * w1v.y; acc[0][6] += av.x * w1v.z; acc[0][7] += av.x * w1v.w;
            acc[1][0] += av.y * w0v.x; acc[1][1] += av.y * w0v.y; acc[1][2] += av.y * w0v.z; acc[1][3] += av.y * w0v.w;
            acc[1][4] += av.y * w1v.x; acc[1][5] += av.y * w1v.y; acc[1][6] += av.y * w1v.z; acc[1][7] += av.y * w1v.w;
            acc[2][0] += av.z * w0v.x; acc[2][1] += av.z * w0v.y; acc[2][2] += av.z * w0v.z; acc[2][3] += av.z * w0v.w;
            acc[2][4] += av.z * w1v.x; acc[2][5] += av.z * w1v.y; acc[2][6] += av.z * w1v.z; acc[2][7] += av.z * w1v.w;
            acc[3][0] += av.w * w0v.x; acc[3][1] += av.w * w0v.y; acc[3][2] += av.w * w0v.z; acc[3][3] += av.w * w0v.w;
            acc[3][4] += av.w * w1v.x; acc[3][5] += av.w * w1v.y; acc[3][6] += av.w * w1v.z; acc[3][7] += av.w * w1v.w;
        }
        __syncthreads();
    }
}

__device__ __forceinline__ void store_tile64(float* __restrict__ C, int ldc, int colBase,
                                             const float acc[4][8])
{
    const int rg4 = (threadIdx.x >> 3) << 2, cg8 = (threadIdx.x & 7) << 3;
#pragma unroll
    for (int i = 0; i < 4; i++) {
        float* p = C + (size_t)(rg4 + i) * ldc + colBase + cg8;
        *(float4*)p       = make_float4(acc[i][0], acc[i][1], acc[i][2], acc[i][3]);
        *(float4*)(p + 4) = make_float4(acc[i][4], acc[i][5], acc[i][6], acc[i][7]);
    }
}

__device__ __forceinline__ float sum4s(const float* p, int i, int stride) {
    return (p[i] + p[stride + i]) + (p[2 * stride + i] + p[3 * stride + i]);
}
__device__ __forceinline__ float sum8s(const float* p, int i) {
    float a = (p[i] + p[65536 + i]) + (p[131072 + i] + p[196608 + i]);
    float b = (p[262144 + i] + p[327680 + i]) + (p[393216 + i] + p[458752 + i]);
    return a + b;
}
__device__ __forceinline__ float sum16(const float* p, int i) {
    float a = (p[i] + p[65536 + i]) + (p[131072 + i] + p[196608 + i]);
    float b = (p[262144 + i] + p[327680 + i]) + (p[393216 + i] + p[458752 + i]);
    float c = (p[524288 + i] + p[589824 + i]) + (p[655360 + i] + p[720896 + i]);
    float d = (p[786432 + i] + p[851968 + i]) + (p[917504 + i] + p[983040 + i]);
    return (a + b) + (c + d);
}

// ---------------- persistent mega-kernel ----------------
__global__ void __launch_bounds__(NTHR, 2) mega_kernel(
    const float* __restrict__ z_seq, const float* __restrict__ z_w,
    const float* __restrict__ Wl2d, const float* __restrict__ temb,
    const float* __restrict__ Wq,  const float* __restrict__ Wk,
    const float* __restrict__ Wv,  const float* __restrict__ Wo,
    const float* __restrict__ Wcq, const float* __restrict__ Wck,
    const float* __restrict__ Wcv, const float* __restrict__ Wco,
    const float* __restrict__ W1,  const float* __restrict__ W2,
    const float* __restrict__ Wout, float* __restrict__ out)
{
    __shared__ float s_q[8 * 64];
    __shared__ float s_sc[8 * 152];
    __shared__ int   s_act[384];
    __shared__ int   s_pos[128], s_tip[128], s_phr[128], s_done[128], s_nxt[128];
    __shared__ float s_gate[128];
    extern __shared__ __align__(16) char dsm[];

    float* sA = (float*)dsm;
    float* sW = (float*)(dsm + 16896);
    __nv_bfloat16* sAH = (__nv_bfloat16*)dsm;
    __nv_bfloat16* sAM = sAH + 9216;
    __nv_bfloat16* sAL = sAM + 9216;
    __nv_bfloat16* sBH = sAL + 9216;
    __nv_bfloat16* sBM = sBH + 2304;
    __nv_bfloat16* sBL = sBM + 2304;

    const int tid = threadIdx.x;
    const int bx  = blockIdx.x;
    const int gid = bx * NTHR + tid;
    const int gsz = NBLK * NTHR;
    float acc[4][8];

    float* wz   = g_f + O_WZ;
    float* mem  = g_f + O_MEM;
    float* ckb  = g_f + O_CK;
    float* cvb  = g_f + O_CV;
    float* qp   = g_f + O_QP;
    float* kp   = g_f + O_KP;
    float* vp   = g_f + O_VP;
    float* sab  = g_f + O_SAB;
    float* p1   = g_f + O_P1;
    float* cqa  = g_f + O_CQA;
    float* cqb  = g_f + O_CQB;
    float* x1   = g_f + O_X1;
    float* cab  = g_f + O_CAB;
    float* p2   = g_f + O_P2;
    float* w1a  = g_f + O_W1A;
    float* w1b  = g_f + O_W1B;
    float* act  = g_f + O_ACT;
    float* x2   = g_f + O_X2;
    float* w2p  = g_f + O_W2P;
    float* wocq = g_f + O_WOCQ;
    float* wcow1= g_f + O_WCOW1;
    float* kc   = g_f + O_KC;
    float* vc   = g_f + O_VC;
    __nv_bfloat16* hidH = (__nv_bfloat16*)(g_f + O_HIDB);
    __nv_bfloat16* hidM = hidH + 65536;
    __nv_bfloat16* hidL = hidM + 65536;
    __nv_bfloat16* wbH  = (__nv_bfloat16*)(g_f + O_WBF);
    __nv_bfloat16* wbM  = wbH + 4096000;
    __nv_bfloat16* wbL  = wbM + 4096000;

    // ---- init ----
    for (int i = gid; i < 49152; i += gsz) wz[i] = z_w[i >> 7] * z_seq[i];
    for (int i = gid; i < OUT_HID; i += gsz) out[i] = 0.f;
    for (int i = gid; i < MAXTOK * 128; i += gsz) g_amax[i] = 0ull;
    for (int i = gid; i < 4096000; i += gsz) {
        int n = i >> 9, k = i & 511;
        float v = Wout[(size_t)k * VOC + n];
        __nv_bfloat16 h = __float2bfloat16(v);
        float r = v - __bfloat162float(h);
        __nv_bfloat16 m = __float2bfloat16(r);
        float r2 = r - __bfloat162float(m);
        wbH[i] = h; wbM[i] = m; wbL[i] = __float2bfloat16(r2);
    }
    for (int i = tid; i < 384; i += NTHR) s_act[i] = (z_w[i] > 0.01f) ? 1 : 0;
    if (tid < 128) {
        s_pos[tid] = 0; s_tip[tid] = 0; s_phr[tid] = 0;
        int a0 = (z_w[tid * 3] > 0.01f) ? 1 : 0;
        s_done[tid] = !a0;
        s_nxt[tid]  = BOSTOK;
        s_gate[tid] = a0 ? 1.f : 0.f;
    }
    gsync();

    // ---- phase A: memories (192) + Wocq = Wo@Wcq (32) + WcoW1 = Wco@W1 (128) ----
    for (int tile = bx; tile < 352; tile += NBLK) {
        if (tile < 192) {
            int by = tile >> 6, cx = tile & 63;
            run_tile64(wz + (size_t)by * 128 * 128, nullptr, 128, Wl2d, 4096, cx * 64,
                       0, 128, sA, sW, acc);
            store_tile64(mem + (size_t)by * 128 * 4096, 4096, cx * 64, acc);
        } else if (tile < 224) {
            int idx = tile - 192, by = idx >> 3, cx = idx & 7;
            run_tile64(Wo + (size_t)by * 65536, nullptr, 512, Wcq, 512, cx * 64,
                       0, 512, sA, sW, acc);
            store_tile64(wocq + (size_t)by * 65536, 512, cx * 64, acc);
        } else {
            int idx = tile - 224, by = idx >> 5, cx = idx & 31;
            run_tile64(Wco + (size_t)by * 65536, nullptr, 512, W1, 2048, cx * 64,
                       0, 512, sA, sW, acc);
            store_tile64(wcow1 + (size_t)by * 128 * 2048, 2048, cx * 64, acc);
        }
    }
    gsync();

    // ---- phase B: ck/cv = mem[3072,512] @ Wck/Wcv : 384 tiles ----
    for (int tile = bx; tile < 384; tile += NBLK) {
        int isv = tile >= 192;
        int idx = isv ? tile - 192 : tile;
        int by = idx >> 3, cx = idx & 7;
        run_tile64(mem + (size_t)by * 65536, nullptr, 512, isv ? Wcv : Wck, 512, cx * 64,
                   0, 512, sA, sW, acc);
        store_tile64((isv ? cvb : ckb) + (size_t)by * 65536, 512, cx * 64, acc);
    }
    gsync();

    // ================= decode loop =================
    for (int t = 0; t < MAXTOK; t++) {
        // ---- QKV: splitK8 (chunk 64), 192 tiles ----
        for (int tile = bx; tile < 192; tile += NBLK) {
            int sel = tile >> 6, rem = tile & 63;
            int ks = rem >> 3, cx = rem & 7;
            const float* W_ = (sel == 0) ? Wq : ((sel == 1) ? Wk : Wv);
            float* C_ = (sel == 0) ? qp : ((sel == 1) ? kp : vp);
            run_tile64(temb, s_nxt, 512, W_, 512, cx * 64, ks * 64, 64, sA, sW, acc);
            store_tile64(C_ + ks * 65536, 512, cx * 64, acc);
        }
        gsync();

        // ---- attention ----
        {
            int wid = tid >> 5, lane = tid & 31;
            int gw = bx * 8 + wid;
            if (gw < 1024) {
                int b = gw >> 3, h = gw & 7;
                int off = b * 512 + h * 64 + lane * 2;
                float2 qv = make_float2(0.f, 0.f), kv2 = qv, vv2 = qv;
#pragma unroll
                for (int j = 0; j < 8; j++) {
                    float2 a = *(const float2*)(qp + j * 65536 + off);
                    float2 c = *(const float2*)(kp + j * 65536 + off);
                    float2 d = *(const float2*)(vp + j * 65536 + off);
                    qv.x += a.x; qv.y += a.y;
                    kv2.x += c.x; kv2.y += c.y;
                    vv2.x += d.x; vv2.y += d.y;
                }
                float* krow = kc + (size_t)(b * 8 + h) * CTOK * 64;
                float* vrow = vc + (size_t)(b * 8 + h) * CTOK * 64;
                *(float2*)(krow + (size_t)t * 64 + lane * 2) = kv2;
                *(float2*)(vrow + (size_t)t * 64 + lane * 2) = vv2;
                float* sqw = s_q + wid * 64;
                float* scw = s_sc + wid * 152;
                *(float2*)(sqw + lane * 2) = qv;
                __syncwarp();
                for (int s = lane; s < t; s += 32) {
                    const float* kr = krow + (size_t)s * 64;
                    float d = 0.f;
#pragma unroll
                    for (int c = 0; c < 16; c++) {
                        float4 kv = *(const float4*)(kr + c * 4);
                        float4 qq = *(const float4*)(sqw + c * 4);
                        d += kv.x * qq.x + kv.y * qq.y + kv.z * qq.z + kv.w * qq.w;
                    }
                    scw[s] = d * 0.125f;
                }
                float pt = wred(qv.x * kv2.x + qv.y * kv2.y) * 0.125f;
                if (lane == 0) scw[t] = pt;
                __syncwarp();
                int n = t + 1;
                float mx = -1e30f;
                for (int s = lane; s < n; s += 32) mx = fmaxf(mx, scw[s]);
                for (int o = 16; o; o >>= 1) mx = fmaxf(mx, __shfl_xor_sync(0xffffffffu, mx, o));
                float sum = 0.f;
                for (int s = lane; s < n; s += 32) {
                    float e = expf(scw[s] - mx);
                    scw[s] = e;
                    sum += e;
                }
                for (int o = 16; o; o >>= 1) sum += __shfl_xor_sync(0xffffffffu, sum, o);
                float inv = 1.0f / sum;
                __syncwarp();
                float a0 = 0.f, a1 = 0.f;
                for (int s = 0; s < t; s++) {
                    float p = scw[s] * inv;
                    float2 vv = *(const float2*)(vrow + (size_t)s * 64 + lane * 2);
                    a0 += p * vv.x;
                    a1 += p * vv.y;
                }
                float ptn = scw[t] * inv;
                a0 += ptn * vv2.x;
                a1 += ptn * vv2.y;
                *(float2*)(sab + off) = make_float2(a0, a1);
            }
        }
        gsync();

        // ---- phase 3: p1 = sa@Wo | cqa = xe@Wcq | cqb = sa@Wocq (splitK8, 192 tiles) ----
        for (int tile = bx; tile < 192; tile += NBLK) {
            int sel = tile >> 6, rem = tile & 63;
            int ks = rem >> 3, cx = rem & 7;
            if (sel == 0) {
                run_tile64(sab, nullptr, 512, Wo, 512, cx * 64, ks * 64, 64, sA, sW, acc);
                store_tile64(p1 + ks * 65536, 512, cx * 64, acc);
            } else if (sel == 1) {
                run_tile64(temb, s_nxt, 512, Wcq, 512, cx * 64, ks * 64, 64, sA, sW, acc);
                store_tile64(cqa + ks * 65536, 512, cx * 64, acc);
            } else {
                run_tile64(sab, nullptr, 512, wocq, 512, cx * 64, ks * 64, 64, sA, sW, acc);
                store_tile64(cqb + ks * 65536, 512, cx * 64, acc);
            }
        }
        gsync();

        // ---- phase 4: x1 materialize || cross-attention ----
        for (int i = gid; i < 65536; i += gsz)
            x1[i] = temb[(size_t)s_nxt[i >> 9] * 512 + (i & 511)] + sum8s(p1, i);
        {
            int wid = tid >> 5, lane = tid & 31;
            int gw = bx * 8 + wid;
            if (gw < 1024) {
                int b = gw >> 3, h = gw & 7;
                int off = b * 512 + h * 64 + lane * 2;
                float qx = 0.f, qy = 0.f;
#pragma unroll
                for (int j = 0; j < 8; j++) {
                    float2 pa = *(const float2*)(cqa + j * 65536 + off);
                    float2 pb = *(const float2*)(cqb + j * 65536 + off);
                    qx += pa.x + pb.x; qy += pa.y + pb.y;
                }
                int phr = s_phr[b];
                int i = phr < 2 ? phr : 2;
                float g = s_gate[b];
                size_t base = (size_t)((b * 3 + i) * 8) * 512 + h * 64 + lane * 2;
                const float* Kp = ckb + base;
                const float* Vp = cvb + base;
                float s[8], mx = -1e30f;
#pragma unroll
                for (int m = 0; m < 8; m++) {
                    float2 kv = *(const float2*)(Kp + m * 512);
                    s[m] = wred(qx * kv.x + qy * kv.y) * 0.125f;
                    mx = fmaxf(mx, s[m]);
                }
                float sum = 0.f;
#pragma unroll
                for (int m = 0; m < 8; m++) { s[m] = expf(s[m] - mx); sum += s[m]; }
                float inv = 1.0f / sum;
                float a0 = 0.f, a1 = 0.f;
#pragma unroll
                for (int m = 0; m < 8; m++) {
                    float2 vv = *(const float2*)(Vp + m * 512);
                    a0 += s[m] * vv.x;
                    a1 += s[m] * vv.y;
                }
                *(float2*)(cab + off) = make_float2(a0 * inv * g, a1 * inv * g);
            }
        }
        gsync();

        // ---- phase 5: p2 = ca@Wco (32) | w1a = x1@W1 (128) | w1b = ca@WcoW1 (128) ----
        for (int tile = bx; tile < 288; tile += NBLK) {
            if (tile < 32) {
                int ks = tile >> 3, cx = tile & 7;
                run_tile64(cab, nullptr, 512, Wco, 512, cx * 64, ks * 128, 128, sA, sW, acc);
                store_tile64(p2 + ks * 65536, 512, cx * 64, acc);
            } else if (tile < 160) {
                int idx = tile - 32, ks = idx >> 5, cx = idx & 31;
                run_tile64(x1, nullptr, 512, W1, 2048, cx * 64, ks * 128, 128, sA, sW, acc);
                store_tile64(w1a + ks * 262144, 2048, cx * 64, acc);
            } else {
                int idx = tile - 160, ks = idx >> 5, cx = idx & 31;
                run_tile64(cab, nullptr, 512, wcow1, 2048, cx * 64, ks * 128, 128, sA, sW, acc);
                store_tile64(w1b + ks * 262144, 2048, cx * 64, acc);
            }
        }
        gsync();

        // ---- phase 6: x2 materialize || act materialize ----
        for (int i = gid; i < 65536; i += gsz)
            x2[i] = x1[i] + sum4s(p2, i, 65536);
        for (int i = gid; i < 262144; i += gsz)
            act[i] = gelu_tanh(sum4s(w1a, i, 262144) + sum4s(w1b, i, 262144));
        gsync();

        // ---- W2: splitK16 (chunk 128), 128 tiles ----
        for (int tile = bx; tile < 128; tile += NBLK) {
            int cx = tile & 7, ks = tile >> 3;
            run_tile64(act, nullptr, 2048, W2, 512, cx * 64, ks * 128, 128, sA, sW, acc);
            store_tile64(w2p + ks * 65536, 512, cx * 64, acc);
        }
        gsync();

        // ---- hid = x2 + sum16(w2p) -> out + bf16 splits ----
        float* hid = out + OUT_HID + (size_t)t * 65536;
        for (int i = gid; i < 65536; i += gsz) {
            float v = x2[i] + sum16(w2p, i);
            hid[i] = v;
            __nv_bfloat16 h = __float2bfloat16(v);
            float r = v - __bfloat162float(h);
            __nv_bfloat16 m = __float2bfloat16(r);
            hidH[i] = h; hidM[i] = m;
            hidL[i] = __float2bfloat16(r - __bfloat162float(m));
        }
        gsync();

        // ---- logits via mma.sync bf16x6 + fused argmax (250 blocks x 32 cols) ----
        if (bx < 250) {
            const int n0 = bx * 32;
            const int w = tid >> 5, lane = tid & 31;
            const int g = lane >> 2, tg = lane & 3;
            float la[4][4];
#pragma unroll
            for (int nt = 0; nt < 4; nt++)
#pragma unroll
                for (int j = 0; j < 4; j++) la[nt][j] = 0.f;

            for (int kchunk = 0; kchunk < 8; kchunk++) {
                for (int i = tid; i < 1024; i += NTHR) {
                    int row = i >> 3, c8 = (i & 7) << 3;
                    size_t src = (size_t)row * 512 + (kchunk << 6) + c8;
                    int dst = row * 72 + c8;
                    *(uint4*)(sAH + dst) = *(const uint4*)(hidH + src);
                    *(uint4*)(sAM + dst) = *(const uint4*)(hidM + src);
                    *(uint4*)(sAL + dst) = *(const uint4*)(hidL + src);
                }
                for (int i = tid; i < 256; i += NTHR) {
                    int row = i >> 3, c8 = (i & 7) << 3;
                    size_t src = (size_t)(n0 + row) * 512 + (kchunk << 6) + c8;
                    int dst = row * 72 + c8;
                    *(uint4*)(sBH + dst) = *(const uint4*)(wbH + src);
                    *(uint4*)(sBM + dst) = *(const uint4*)(wbM + src);
                    *(uint4*)(sBL + dst) = *(const uint4*)(wbL + src);
                }
                __syncthreads();
#pragma unroll
                for (int ks = 0; ks < 4; ks++) {
                    int ab = (w * 16 + g) * 72 + (ks << 4) + (tg << 1);
                    unsigned aH0 = *(const unsigned*)(sAH + ab);
                    unsigned aH1 = *(const unsigned*)(sAH + ab + 576);
                    unsigned aH2 = *(const unsigned*)(sAH + ab + 8);
                    unsigned aH3 = *(const unsigned*)(sAH + ab + 584);
                    unsigned aM0 = *(const unsigned*)(sAM + ab);
                    unsigned aM1 = *(const unsigned*)(sAM + ab + 576);
                    unsigned aM2 = *(const unsigned*)(sAM + ab + 8);
                    unsigned aM3 = *(const unsigned*)(sAM + ab + 584);
                    unsigned aL0 = *(const unsigned*)(sAL + ab);
                    unsigned aL1 = *(const unsigned*)(sAL + ab + 576);
                    unsigned aL2 = *(const unsigned*)(sAL + ab + 8);
                    unsigned aL3 = *(const unsigned*)(sAL + ab + 584);
#pragma unroll
                    for (int nt = 0; nt < 4; nt++) {
                        int bb = (nt * 8 + g) * 72 + (ks << 4) + (tg << 1);
                        unsigned bH0 = *(const unsigned*)(sBH + bb);
                        unsigned bH1 = *(const unsigned*)(sBH + bb + 8);
                        unsigned bM0 = *(const unsigned*)(sBM + bb);
                        unsigned bM1 = *(const unsigned*)(sBM + bb + 8);
                        unsigned bL0 = *(const unsigned*)(sBL + bb);
                        unsigned bL1 = *(const unsigned*)(sBL + bb + 8);
                        mma_bf16(la[nt], aH0, aH1, aH2, aH3, bH0, bH1);
                        mma_bf16(la[nt], aH0, aH1, aH2, aH3, bM0, bM1);
                        mma_bf16(la[nt], aM0, aM1, aM2, aM3, bH0, bH1);
                        mma_bf16(la[nt], aM0, aM1, aM2, aM3, bM0, bM1);
                        mma_bf16(la[nt], aH0, aH1, aH2, aH3, bL0, bL1);
                        mma_bf16(la[nt], aL0, aL1, aL2, aL3, bH0, bH1);
                    }
                }
                __syncthreads();
            }
            int r0 = w * 16 + g, r1 = r0 + 8;
            unsigned long long b0 = 0ull, b1 = 0ull;
#pragma unroll
            for (int nt = 0; nt < 4; nt++) {
                int col = n0 + nt * 8 + (tg << 1);
                unsigned u;
                u = __float_as_uint(la[nt][0]);
                u = (u & 0x80000000u) ? ~u : (u | 0x80000000u);
                b0 = umax64(b0, ((unsigned long long)u << 32) | (unsigned)(VOC - 1 - col));
                u = __float_as_uint(la[nt][1]);
                u = (u & 0x80000000u) ? ~u : (u | 0x80000000u);
                b0 = umax64(b0, ((unsigned long long)u << 32) | (unsigned)(VOC - 2 - col));
                u = __float_as_uint(la[nt][2]);
                u = (u & 0x80000000u) ? ~u : (u | 0x80000000u);
                b1 = umax64(b1, ((unsigned long long)u << 32) | (unsigned)(VOC - 1 - col));
                u = __float_as_uint(la[nt][3]);
                u = (u & 0x80000000u) ? ~u : (u | 0x80000000u);
                b1 = umax64(b1, ((unsigned long long)u << 32) | (unsigned)(VOC - 2 - col));
            }
            b0 = umax64(b0, __shfl_xor_sync(0xffffffffu, b0, 1));
            b0 = umax64(b0, __shfl_xor_sync(0xffffffffu, b0, 2));
            b1 = umax64(b1, __shfl_xor_sync(0xffffffffu, b1, 1));
            b1 = umax64(b1, __shfl_xor_sync(0xffffffffu, b1, 2));
            if (tg == 0) {
                atomicMax(&g_amax[t * 128 + r0], b0);
                atomicMax(&g_amax[t * 128 + r1], b1);
            }
        }
        gsync();

        // ---- state machine (replicated; block 0 writes outputs) ----
        if (tid < 128) {
            int b = tid;
            unsigned long long key = g_amax[t * 128 + b];
            int col = (VOC - 1) - (int)(key & 0xffffffffu);
            int pos = s_pos[b], tip = s_tip[b], phr = s_phr[b], done = s_done[b];
            int live = !done;
            if (live && bx == 0) {
                out[b * MAXTOK + pos] = (float)col;
                out[OUT_GENM + b * MAXTOK + pos] = 1.0f;
            }
            pos += live;
            tip += live;
            int eos = (col == EOSTOK) && (tip >= 1);
            int sw = (eos || (tip >= MAXPER)) && live;
            phr += sw;
            if (sw) tip = 0;
            int cp = phr < 2 ? phr : 2;
            if (sw && phr < KPH && bx == 0) out[OUT_BOUNDS + b * 3 + cp] = (float)pos;
            done = done || (phr >= KPH) || (sw && !s_act[b * 3 + cp]);
            s_pos[b] = pos;
            s_tip[b] = tip;
            s_phr[b] = phr;
            s_done[b] = done;
            s_nxt[b] = col;
            s_gate[b] = (s_act[b * 3 + cp] && !done) ? 1.0f : 0.0f;
        }
        __syncthreads();
    }
}

// ---------------- host ----------------
extern "C" void kernel_launch(void* const* d_in, const int* in_sizes, int n_in,
                              void* d_out, int out_size)
{
    (void)in_sizes; (void)n_in; (void)out_size;
    const int dynBytes = 69120;
    cudaFuncSetAttribute(mega_kernel, cudaFuncAttributeMaxDynamicSharedMemorySize, dynBytes);
    mega_kernel<<<NBLK, NTHR, dynBytes>>>(
        (const float*)d_in[0],  (const float*)d_in[1],  (const float*)d_in[2],
        (const float*)d_in[3],  (const float*)d_in[4],  (const float*)d_in[5],
        (const float*)d_in[6],  (const float*)d_in[7],  (const float*)d_in[8],
        (const float*)d_in[9],  (const float*)d_in[10], (const float*)d_in[11],
        (const float*)d_in[12], (const float*)d_in[13], (const float*)d_in[14],
        (float*)d_out);
}